// round 1
// baseline (speedup 1.0000x reference)
#include <cuda_runtime.h>
#include <math.h>

// Problem dims (fixed by the reference)
#define B_  4
#define S_  2048
#define D_  1024
#define MS  (B_*S_)              // 8192 total rows
static __device__ __constant__ float kScale = 0.03125f;  // 1/sqrt(1024)

// Scratch (allocation-free rule: __device__ globals)
__device__ float g_Q[MS * D_];          // 32 MB
__device__ float g_K[MS * D_];          // 32 MB
__device__ float g_V[MS * D_];          // 32 MB
__device__ float g_S[(size_t)B_ * S_ * S_];  // 64 MB scores / attn

// ---------------------------------------------------------------------------
// Shared 128x128x8 tile micro-kernel: 8x8 per-thread accumulator, 256 threads
// ---------------------------------------------------------------------------
__device__ __forceinline__ void mma_tile(const float (&As)[8][128],
                                         const float (&Bs)[8][128],
                                         float (&acc)[8][8], int ty, int tx) {
#pragma unroll
    for (int k = 0; k < 8; k++) {
        float ar[8], br[8];
#pragma unroll
        for (int i = 0; i < 8; i++) ar[i] = As[k][ty * 8 + i];
#pragma unroll
        for (int j = 0; j < 8; j++) br[j] = Bs[k][tx * 8 + j];
#pragma unroll
        for (int i = 0; i < 8; i++)
#pragma unroll
            for (int j = 0; j < 8; j++) acc[i][j] += ar[i] * br[j];
    }
}

// ---------------------------------------------------------------------------
// Kernel 1: fused QKV projection.  C = x[8192,1024] @ W[1024,1024] + b
// blockIdx.z in {0,1,2} selects (Wq,bq,g_Q) / (Wk,bk,g_K) / (Wv,bv,g_V)
// ---------------------------------------------------------------------------
__global__ __launch_bounds__(256, 2) void proj_qkv_kernel(
    const float* __restrict__ x,
    const float* __restrict__ Wq, const float* __restrict__ bq,
    const float* __restrict__ Wk, const float* __restrict__ bk,
    const float* __restrict__ Wv, const float* __restrict__ bv) {
    __shared__ float As[8][128];
    __shared__ float Bs[8][128];

    const float* W;
    const float* bias;
    float* C;
    if (blockIdx.z == 0)      { W = Wq; bias = bq; C = g_Q; }
    else if (blockIdx.z == 1) { W = Wk; bias = bk; C = g_K; }
    else                      { W = Wv; bias = bv; C = g_V; }

    const int tid = threadIdx.x;
    const int bm = blockIdx.y * 128;
    const int bn = blockIdx.x * 128;

    const int aRow = tid >> 1, aCol = (tid & 1) * 4;   // A tile 128x8
    const int bRow = tid >> 5, bCol = (tid & 31) * 4;  // B tile 8x128
    const int tx = tid & 15, ty = tid >> 4;

    float acc[8][8] = {};
    const float* Ap = x + (size_t)(bm + aRow) * D_ + aCol;
    const float* Bp = W + (size_t)bRow * D_ + bn + bCol;

    for (int k0 = 0; k0 < D_; k0 += 8) {
        float4 a4 = *(const float4*)Ap;
        As[aCol + 0][aRow] = a4.x;
        As[aCol + 1][aRow] = a4.y;
        As[aCol + 2][aRow] = a4.z;
        As[aCol + 3][aRow] = a4.w;
        *(float4*)&Bs[bRow][bCol] = *(const float4*)Bp;
        __syncthreads();
        mma_tile(As, Bs, acc, ty, tx);
        __syncthreads();
        Ap += 8;
        Bp += (size_t)8 * D_;
    }

#pragma unroll
    for (int i = 0; i < 8; i++) {
        float* Crow = C + (size_t)(bm + ty * 8 + i) * D_ + bn + tx * 8;
#pragma unroll
        for (int j = 0; j < 8; j += 4) {
            const int col = bn + tx * 8 + j;
            float4 o;
            o.x = acc[i][j + 0] + bias[col + 0];
            o.y = acc[i][j + 1] + bias[col + 1];
            o.z = acc[i][j + 2] + bias[col + 2];
            o.w = acc[i][j + 3] + bias[col + 3];
            *(float4*)(Crow + j) = o;
        }
    }
}

// ---------------------------------------------------------------------------
// Kernel 2: scores = (Q @ K^T) * scale  per batch (blockIdx.z)
// Both operands row-major [rows, D]; B consumed transposed.
// ---------------------------------------------------------------------------
__global__ __launch_bounds__(256, 2) void scores_kernel() {
    __shared__ float As[8][128];
    __shared__ float Bs[8][128];

    const int b = blockIdx.z;
    const float* Q  = g_Q + (size_t)b * S_ * D_;
    const float* Kp = g_K + (size_t)b * S_ * D_;
    float* C = g_S + (size_t)b * S_ * S_;

    const int tid = threadIdx.x;
    const int bm = blockIdx.y * 128;
    const int bn = blockIdx.x * 128;

    const int r = tid >> 1, c4 = (tid & 1) * 4;  // both tiles: 128 rows x 8 k
    const int tx = tid & 15, ty = tid >> 4;

    float acc[8][8] = {};
    const float* Ap = Q + (size_t)(bm + r) * D_ + c4;
    const float* Bp = Kp + (size_t)(bn + r) * D_ + c4;

    for (int k0 = 0; k0 < D_; k0 += 8) {
        float4 a4 = *(const float4*)Ap;
        As[c4 + 0][r] = a4.x;
        As[c4 + 1][r] = a4.y;
        As[c4 + 2][r] = a4.z;
        As[c4 + 3][r] = a4.w;
        float4 b4 = *(const float4*)Bp;
        Bs[c4 + 0][r] = b4.x;
        Bs[c4 + 1][r] = b4.y;
        Bs[c4 + 2][r] = b4.z;
        Bs[c4 + 3][r] = b4.w;
        __syncthreads();
        mma_tile(As, Bs, acc, ty, tx);
        __syncthreads();
        Ap += 8;
        Bp += 8;
    }

    const float sc = kScale;
#pragma unroll
    for (int i = 0; i < 8; i++) {
        float* Crow = C + (size_t)(bm + ty * 8 + i) * S_ + bn + tx * 8;
#pragma unroll
        for (int j = 0; j < 8; j += 4) {
            float4 o;
            o.x = acc[i][j + 0] * sc;
            o.y = acc[i][j + 1] * sc;
            o.z = acc[i][j + 2] * sc;
            o.w = acc[i][j + 3] * sc;
            *(float4*)(Crow + j) = o;
        }
    }
}

// ---------------------------------------------------------------------------
// Kernel 3: row softmax over g_S.  One block per row (8192 rows x 2048 cols).
// ---------------------------------------------------------------------------
__global__ __launch_bounds__(256) void softmax_kernel() {
    const size_t row = blockIdx.x;
    float* p = g_S + row * (size_t)S_;
    const int tid = threadIdx.x;

    __shared__ float red[256];

    float v[8];
    float m = -INFINITY;
#pragma unroll
    for (int i = 0; i < 8; i++) {
        v[i] = p[tid + i * 256];
        m = fmaxf(m, v[i]);
    }
    red[tid] = m;
    __syncthreads();
    for (int s = 128; s > 0; s >>= 1) {
        if (tid < s) red[tid] = fmaxf(red[tid], red[tid + s]);
        __syncthreads();
    }
    m = red[0];
    __syncthreads();

    float sum = 0.f;
#pragma unroll
    for (int i = 0; i < 8; i++) {
        v[i] = __expf(v[i] - m);
        sum += v[i];
    }
    red[tid] = sum;
    __syncthreads();
    for (int s = 128; s > 0; s >>= 1) {
        if (tid < s) red[tid] += red[tid + s];
        __syncthreads();
    }
    const float inv = 1.0f / red[0];
#pragma unroll
    for (int i = 0; i < 8; i++) p[tid + i * 256] = v[i] * inv;
}

// ---------------------------------------------------------------------------
// Kernel 4: out = attn @ V  per batch (blockIdx.z).  M=2048,N=1024,K=2048
// ---------------------------------------------------------------------------
__global__ __launch_bounds__(256, 2) void av_kernel(float* __restrict__ out) {
    __shared__ float As[8][128];
    __shared__ float Bs[8][128];

    const int b = blockIdx.z;
    const float* A = g_S + (size_t)b * S_ * S_;
    const float* V = g_V + (size_t)b * S_ * D_;
    float* C = out + (size_t)b * S_ * D_;

    const int tid = threadIdx.x;
    const int bm = blockIdx.y * 128;
    const int bn = blockIdx.x * 128;

    const int aRow = tid >> 1, aCol = (tid & 1) * 4;
    const int bRow = tid >> 5, bCol = (tid & 31) * 4;
    const int tx = tid & 15, ty = tid >> 4;

    float acc[8][8] = {};
    const float* Ap = A + (size_t)(bm + aRow) * S_ + aCol;
    const float* Bp = V + (size_t)bRow * D_ + bn + bCol;

    for (int k0 = 0; k0 < S_; k0 += 8) {
        float4 a4 = *(const float4*)Ap;
        As[aCol + 0][aRow] = a4.x;
        As[aCol + 1][aRow] = a4.y;
        As[aCol + 2][aRow] = a4.z;
        As[aCol + 3][aRow] = a4.w;
        *(float4*)&Bs[bRow][bCol] = *(const float4*)Bp;
        __syncthreads();
        mma_tile(As, Bs, acc, ty, tx);
        __syncthreads();
        Ap += 8;
        Bp += (size_t)8 * D_;
    }

#pragma unroll
    for (int i = 0; i < 8; i++) {
        float* Crow = C + (size_t)(bm + ty * 8 + i) * D_ + bn + tx * 8;
#pragma unroll
        for (int j = 0; j < 8; j += 4) {
            float4 o = make_float4(acc[i][j], acc[i][j + 1],
                                   acc[i][j + 2], acc[i][j + 3]);
            *(float4*)(Crow + j) = o;
        }
    }
}

// ---------------------------------------------------------------------------
// Launch: 4 graph-capturable kernel launches, no sync, no allocation.
// ---------------------------------------------------------------------------
extern "C" void kernel_launch(void* const* d_in, const int* in_sizes, int n_in,
                              void* d_out, int out_size) {
    const float* x  = (const float*)d_in[0];
    const float* Wq = (const float*)d_in[1];
    const float* bq = (const float*)d_in[2];
    const float* Wk = (const float*)d_in[3];
    const float* bk = (const float*)d_in[4];
    const float* Wv = (const float*)d_in[5];
    const float* bv = (const float*)d_in[6];
    float* out = (float*)d_out;

    dim3 gProj(D_ / 128, MS / 128, 3);   // (8, 64, 3)
    proj_qkv_kernel<<<gProj, 256>>>(x, Wq, bq, Wk, bk, Wv, bv);

    dim3 gScores(S_ / 128, S_ / 128, B_);  // (16, 16, 4)
    scores_kernel<<<gScores, 256>>>();

    softmax_kernel<<<B_ * S_, 256>>>();    // 8192 rows

    dim3 gOut(D_ / 128, S_ / 128, B_);     // (8, 16, 4)
    av_kernel<<<gOut, 256>>>(out);
}

// round 3
// speedup vs baseline: 1.9658x; 1.9658x over previous
#include <cuda_runtime.h>
#include <cuda_bf16.h>
#include <stdint.h>
#include <math.h>

#define B_  4
#define S_  2048
#define D_  1024
#define MS  (B_*S_)
#define BK  16

typedef __nv_bfloat16 bf16;

// ---------------------------------------------------------------------------
// Device-global scratch (allocation-free rule)
// ---------------------------------------------------------------------------
__device__ bf16 g_xh[MS * D_], g_xl[MS * D_];                 // x split
__device__ bf16 g_Wth[3][D_ * D_], g_Wtl[3][D_ * D_];         // W^T split [n][k]
__device__ bf16 g_Qh[MS * D_], g_Ql[MS * D_];
__device__ bf16 g_Kh[MS * D_], g_Kl[MS * D_];
__device__ bf16 g_Vh[MS * D_], g_Vl[MS * D_];
__device__ bf16 g_Vth[MS * D_], g_Vtl[MS * D_];               // V^T per batch [d][t]
__device__ float g_S[(size_t)B_ * S_ * S_];                   // scores fp32
__device__ bf16 g_Ph[(size_t)B_ * S_ * S_], g_Pl[(size_t)B_ * S_ * S_]; // attn split

// ---------------------------------------------------------------------------
// Helpers
// ---------------------------------------------------------------------------
__device__ __forceinline__ void split1(float v, bf16& h, bf16& l) {
    h = __float2bfloat16_rn(v);
    l = __float2bfloat16_rn(v - __bfloat162float(h));
}

// element offset of 8-bf16 chunk (row, chunk) with xor swizzle (conflict-free)
__device__ __forceinline__ uint32_t swz_off(int row, int chunk) {
    return (uint32_t)((row * 2 + (chunk ^ ((row >> 2) & 1))) * 8);
}

__device__ __forceinline__ void ldsm4(uint32_t r[4], const bf16* p) {
    uint32_t a = (uint32_t)__cvta_generic_to_shared(p);
    asm volatile("ldmatrix.sync.aligned.m8n8.x4.shared.b16 {%0,%1,%2,%3}, [%4];"
                 : "=r"(r[0]), "=r"(r[1]), "=r"(r[2]), "=r"(r[3]) : "r"(a));
}

__device__ __forceinline__ void mma_bf16(float c[4], const uint32_t a[4],
                                         const uint32_t b0, const uint32_t b1) {
    asm volatile(
        "mma.sync.aligned.m16n8k16.row.col.f32.bf16.bf16.f32 "
        "{%0,%1,%2,%3},{%4,%5,%6,%7},{%8,%9},{%0,%1,%2,%3};"
        : "+f"(c[0]), "+f"(c[1]), "+f"(c[2]), "+f"(c[3])
        : "r"(a[0]), "r"(a[1]), "r"(a[2]), "r"(a[3]), "r"(b0), "r"(b1));
}

// ---------------------------------------------------------------------------
// Shared GEMM mainloop: C128x128 block, A[m][k] row-major, B[n][k] row-major,
// both as bf16 hi/lo pairs.  acc += Ah*Bh + Ah*Bl + Al*Bh.
// 256 threads, 8 warps in 2(m) x 4(n), warp tile 64x32.
// ---------------------------------------------------------------------------
__device__ __forceinline__ void gemm_core(
    const bf16* __restrict__ Ah, const bf16* __restrict__ Al, int lda,
    const bf16* __restrict__ Bh, const bf16* __restrict__ Bl, int ldb,
    int bm, int bn, int K, float acc[4][4][4])
{
    __shared__ __align__(16) bf16 sAh[2][128 * BK], sAl[2][128 * BK];
    __shared__ __align__(16) bf16 sBh[2][128 * BK], sBl[2][128 * BK];

    const int tid = threadIdx.x, lane = tid & 31, warp = tid >> 5;
    const int wm = (warp >> 2) * 64, wn = (warp & 3) * 32;

    // gmem->smem copy mapping: thread t handles (row = t>>1, chunk = t&1)
    const int cr = tid >> 1, cc = tid & 1;
    const bf16* pAh = Ah + (size_t)(bm + cr) * lda + cc * 8;
    const bf16* pAl = Al + (size_t)(bm + cr) * lda + cc * 8;
    const bf16* pBh = Bh + (size_t)(bn + cr) * ldb + cc * 8;
    const bf16* pBl = Bl + (size_t)(bn + cr) * ldb + cc * 8;
    const uint32_t so = swz_off(cr, cc);

    *(uint4*)(sAh[0] + so) = *(const uint4*)pAh;
    *(uint4*)(sAl[0] + so) = *(const uint4*)pAl;
    *(uint4*)(sBh[0] + so) = *(const uint4*)pBh;
    *(uint4*)(sBl[0] + so) = *(const uint4*)pBl;
    __syncthreads();

    // ldmatrix lane mapping
    const int arow = (lane & 7) + 8 * ((lane >> 3) & 1);
    const int achk = lane >> 4;
    const int brow = (lane & 7) + 8 * ((lane >> 4) & 1);
    const int bchk = (lane >> 3) & 1;

    const int KT = K / BK;
    for (int kt = 0; kt < KT; ++kt) {
        const int buf = kt & 1;
        uint4 nAh, nAl, nBh, nBl;
        const bool nxt = (kt + 1) < KT;
        if (nxt) {
            pAh += BK; pAl += BK; pBh += BK; pBl += BK;
            nAh = *(const uint4*)pAh;
            nAl = *(const uint4*)pAl;
            nBh = *(const uint4*)pBh;
            nBl = *(const uint4*)pBl;
        }

        uint32_t ah[4][4], al[4][4], bh[2][4], bl[2][4];
#pragma unroll
        for (int i = 0; i < 4; i++) {
            uint32_t o = swz_off(wm + 16 * i + arow, achk);
            ldsm4(ah[i], sAh[buf] + o);
            ldsm4(al[i], sAl[buf] + o);
        }
#pragma unroll
        for (int p = 0; p < 2; p++) {
            uint32_t o = swz_off(wn + 16 * p + brow, bchk);
            ldsm4(bh[p], sBh[buf] + o);
            ldsm4(bl[p], sBl[buf] + o);
        }
#pragma unroll
        for (int i = 0; i < 4; i++)
#pragma unroll
            for (int j = 0; j < 4; j++) {
                const int p = j >> 1, s = (j & 1) * 2;
                mma_bf16(acc[i][j], ah[i], bh[p][s], bh[p][s + 1]);
                mma_bf16(acc[i][j], ah[i], bl[p][s], bl[p][s + 1]);
                mma_bf16(acc[i][j], al[i], bh[p][s], bh[p][s + 1]);
            }

        if (nxt) {
            *(uint4*)(sAh[buf ^ 1] + so) = nAh;
            *(uint4*)(sAl[buf ^ 1] + so) = nAl;
            *(uint4*)(sBh[buf ^ 1] + so) = nBh;
            *(uint4*)(sBl[buf ^ 1] + so) = nBl;
            __syncthreads();
        }
    }
}

// ---------------------------------------------------------------------------
// Conversion kernels
// ---------------------------------------------------------------------------
__global__ void convert_x_kernel(const float* __restrict__ x) {
    size_t i = ((size_t)blockIdx.x * 256 + threadIdx.x) * 4;
    float4 v = *(const float4*)(x + i);
    bf16 h0, l0, h1, l1, h2, l2, h3, l3;
    split1(v.x, h0, l0); split1(v.y, h1, l1);
    split1(v.z, h2, l2); split1(v.w, h3, l3);
    *(__nv_bfloat162*)(g_xh + i)     = __halves2bfloat162(h0, h1);
    *(__nv_bfloat162*)(g_xh + i + 2) = __halves2bfloat162(h2, h3);
    *(__nv_bfloat162*)(g_xl + i)     = __halves2bfloat162(l0, l1);
    *(__nv_bfloat162*)(g_xl + i + 2) = __halves2bfloat162(l2, l3);
}

// W [k][n] fp32 -> Wt [n][k] bf16 hi/lo (transpose + split)
__global__ void convert_Wt_kernel(const float* __restrict__ Wq,
                                  const float* __restrict__ Wk,
                                  const float* __restrict__ Wv) {
    const float* W = blockIdx.z == 0 ? Wq : blockIdx.z == 1 ? Wk : Wv;
    bf16* Oh = g_Wth[blockIdx.z];
    bf16* Ol = g_Wtl[blockIdx.z];
    __shared__ float t[32][33];
    const int k0 = blockIdx.y * 32, n0 = blockIdx.x * 32;
    const int tx = threadIdx.x, ty = threadIdx.y;
#pragma unroll
    for (int r = 0; r < 32; r += 8)
        t[ty + r][tx] = W[(size_t)(k0 + ty + r) * D_ + n0 + tx];
    __syncthreads();
#pragma unroll
    for (int r = 0; r < 32; r += 8) {
        float v = t[tx][ty + r];  // = W[k0+tx][n0+ty+r]
        bf16 h, l; split1(v, h, l);
        size_t o = (size_t)(n0 + ty + r) * D_ + k0 + tx;
        Oh[o] = h; Ol[o] = l;
    }
}

// V [b][t][d] bf16 hi/lo -> Vt [b][d][t]
__global__ void transpose_V_kernel() {
    __shared__ bf16 th[32][33], tl[32][33];
    const int b = blockIdx.z;
    const int t0 = blockIdx.x * 32, d0 = blockIdx.y * 32;
    const int tx = threadIdx.x, ty = threadIdx.y;
    const bf16* Vh = g_Vh + (size_t)b * S_ * D_;
    const bf16* Vl = g_Vl + (size_t)b * S_ * D_;
#pragma unroll
    for (int r = 0; r < 32; r += 8) {
        size_t o = (size_t)(t0 + ty + r) * D_ + d0 + tx;
        th[ty + r][tx] = Vh[o];
        tl[ty + r][tx] = Vl[o];
    }
    __syncthreads();
    bf16* Oth = g_Vth + (size_t)b * D_ * S_;
    bf16* Otl = g_Vtl + (size_t)b * D_ * S_;
#pragma unroll
    for (int r = 0; r < 32; r += 8) {
        size_t o = (size_t)(d0 + ty + r) * S_ + t0 + tx;
        Oth[o] = th[tx][ty + r];
        Otl[o] = tl[tx][ty + r];
    }
}

// ---------------------------------------------------------------------------
// GEMM 1: QKV projection.  C = x @ W + b, outputs bf16 hi/lo row-major
// ---------------------------------------------------------------------------
__global__ __launch_bounds__(256, 1) void gemm_proj_kernel(
    const float* __restrict__ bqp, const float* __restrict__ bkp,
    const float* __restrict__ bvp) {
    const int z = blockIdx.z;
    const float* bias = z == 0 ? bqp : z == 1 ? bkp : bvp;
    bf16* Ch = z == 0 ? g_Qh : z == 1 ? g_Kh : g_Vh;
    bf16* Cl = z == 0 ? g_Ql : z == 1 ? g_Kl : g_Vl;
    const int bm = blockIdx.y * 128, bn = blockIdx.x * 128;

    float acc[4][4][4] = {};
    gemm_core(g_xh, g_xl, D_, g_Wth[z], g_Wtl[z], D_, bm, bn, D_, acc);

    const int lane = threadIdx.x & 31, warp = threadIdx.x >> 5;
    const int wm = (warp >> 2) * 64, wn = (warp & 3) * 32;
    const int g = lane >> 2, t = lane & 3;
#pragma unroll
    for (int i = 0; i < 4; i++)
#pragma unroll
        for (int j = 0; j < 4; j++) {
            const int col = bn + wn + 8 * j + 2 * t;
            const float b0 = bias[col], b1 = bias[col + 1];
            const int r0 = bm + wm + 16 * i + g;
            bf16 h0, l0, h1, l1;
            split1(acc[i][j][0] + b0, h0, l0);
            split1(acc[i][j][1] + b1, h1, l1);
            *(__nv_bfloat162*)(Ch + (size_t)r0 * D_ + col) = __halves2bfloat162(h0, h1);
            *(__nv_bfloat162*)(Cl + (size_t)r0 * D_ + col) = __halves2bfloat162(l0, l1);
            split1(acc[i][j][2] + b0, h0, l0);
            split1(acc[i][j][3] + b1, h1, l1);
            *(__nv_bfloat162*)(Ch + (size_t)(r0 + 8) * D_ + col) = __halves2bfloat162(h0, h1);
            *(__nv_bfloat162*)(Cl + (size_t)(r0 + 8) * D_ + col) = __halves2bfloat162(l0, l1);
        }
}

// ---------------------------------------------------------------------------
// GEMM 2: scores = (Q @ K^T) * scale  (fp32 out)
// ---------------------------------------------------------------------------
__global__ __launch_bounds__(256, 1) void gemm_scores_kernel() {
    const int b = blockIdx.z;
    const size_t off = (size_t)b * S_ * D_;
    const int bm = blockIdx.y * 128, bn = blockIdx.x * 128;

    float acc[4][4][4] = {};
    gemm_core(g_Qh + off, g_Ql + off, D_, g_Kh + off, g_Kl + off, D_, bm, bn, D_, acc);

    float* C = g_S + (size_t)b * S_ * S_;
    const int lane = threadIdx.x & 31, warp = threadIdx.x >> 5;
    const int wm = (warp >> 2) * 64, wn = (warp & 3) * 32;
    const int g = lane >> 2, t = lane & 3;
    const float sc = 0.03125f;
#pragma unroll
    for (int i = 0; i < 4; i++)
#pragma unroll
        for (int j = 0; j < 4; j++) {
            const int col = bn + wn + 8 * j + 2 * t;
            const int r0 = bm + wm + 16 * i + g;
            float2 v0 = make_float2(acc[i][j][0] * sc, acc[i][j][1] * sc);
            float2 v1 = make_float2(acc[i][j][2] * sc, acc[i][j][3] * sc);
            *(float2*)(C + (size_t)r0 * S_ + col) = v0;
            *(float2*)(C + (size_t)(r0 + 8) * S_ + col) = v1;
        }
}

// ---------------------------------------------------------------------------
// Softmax: fp32 scores -> attn bf16 hi/lo
// ---------------------------------------------------------------------------
__global__ __launch_bounds__(256) void softmax_kernel() {
    const size_t row = blockIdx.x;
    const float* p = g_S + row * (size_t)S_;
    bf16* oh = g_Ph + row * (size_t)S_;
    bf16* ol = g_Pl + row * (size_t)S_;
    const int tid = threadIdx.x;

    __shared__ float red[256];

    float v[8];
    float m = -INFINITY;
#pragma unroll
    for (int i = 0; i < 8; i++) {
        v[i] = p[tid + i * 256];
        m = fmaxf(m, v[i]);
    }
    red[tid] = m;
    __syncthreads();
    for (int s = 128; s > 0; s >>= 1) {
        if (tid < s) red[tid] = fmaxf(red[tid], red[tid + s]);
        __syncthreads();
    }
    m = red[0];
    __syncthreads();

    float sum = 0.f;
#pragma unroll
    for (int i = 0; i < 8; i++) {
        v[i] = __expf(v[i] - m);
        sum += v[i];
    }
    red[tid] = sum;
    __syncthreads();
    for (int s = 128; s > 0; s >>= 1) {
        if (tid < s) red[tid] += red[tid + s];
        __syncthreads();
    }
    const float inv = 1.0f / red[0];
#pragma unroll
    for (int i = 0; i < 8; i++) {
        bf16 h, l;
        split1(v[i] * inv, h, l);
        oh[tid + i * 256] = h;
        ol[tid + i * 256] = l;
    }
}

// ---------------------------------------------------------------------------
// GEMM 3: out = attn @ V  (fp32 out)
// ---------------------------------------------------------------------------
__global__ __launch_bounds__(256, 1) void gemm_av_kernel(float* __restrict__ out) {
    const int b = blockIdx.z;
    const bf16* Ah = g_Ph + (size_t)b * S_ * S_;
    const bf16* Al = g_Pl + (size_t)b * S_ * S_;
    const bf16* Bh = g_Vth + (size_t)b * D_ * S_;
    const bf16* Bl = g_Vtl + (size_t)b * D_ * S_;
    const int bm = blockIdx.y * 128, bn = blockIdx.x * 128;

    float acc[4][4][4] = {};
    gemm_core(Ah, Al, S_, Bh, Bl, S_, bm, bn, S_, acc);

    float* C = out + (size_t)b * S_ * D_;
    const int lane = threadIdx.x & 31, warp = threadIdx.x >> 5;
    const int wm = (warp >> 2) * 64, wn = (warp & 3) * 32;
    const int g = lane >> 2, t = lane & 3;
#pragma unroll
    for (int i = 0; i < 4; i++)
#pragma unroll
        for (int j = 0; j < 4; j++) {
            const int col = bn + wn + 8 * j + 2 * t;
            const int r0 = bm + wm + 16 * i + g;
            *(float2*)(C + (size_t)r0 * D_ + col) =
                make_float2(acc[i][j][0], acc[i][j][1]);
            *(float2*)(C + (size_t)(r0 + 8) * D_ + col) =
                make_float2(acc[i][j][2], acc[i][j][3]);
        }
}

// ---------------------------------------------------------------------------
// Launch
// ---------------------------------------------------------------------------
extern "C" void kernel_launch(void* const* d_in, const int* in_sizes, int n_in,
                              void* d_out, int out_size) {
    const float* x  = (const float*)d_in[0];
    const float* Wq = (const float*)d_in[1];
    const float* bq = (const float*)d_in[2];
    const float* Wk = (const float*)d_in[3];
    const float* bk = (const float*)d_in[4];
    const float* Wv = (const float*)d_in[5];
    const float* bv = (const float*)d_in[6];
    float* out = (float*)d_out;

    convert_x_kernel<<<(MS * D_) / 1024, 256>>>(x);
    convert_Wt_kernel<<<dim3(32, 32, 3), dim3(32, 8)>>>(Wq, Wk, Wv);

    gemm_proj_kernel<<<dim3(D_ / 128, MS / 128, 3), 256>>>(bq, bk, bv);

    transpose_V_kernel<<<dim3(S_ / 32, D_ / 32, B_), dim3(32, 8)>>>();

    gemm_scores_kernel<<<dim3(S_ / 128, S_ / 128, B_), 256>>>();

    softmax_kernel<<<B_ * S_, 256>>>();

    gemm_av_kernel<<<dim3(D_ / 128, S_ / 128, B_), 256>>>(out);
}

// round 5
// speedup vs baseline: 2.2705x; 1.1550x over previous
#include <cuda_runtime.h>
#include <cuda_bf16.h>
#include <stdint.h>
#include <math.h>

#define B_  4
#define S_  2048
#define D_  1024
#define MS  (B_*S_)
#define BK  16
#define NSTG 5
#define ARR_B (128*BK*2)          // bytes per operand array per stage (4 KB)
#define STAGE_B (4*ARR_B)         // 16 KB: [Ah][Al][Bh][Bl]
#define SMEM_DYN (NSTG*STAGE_B)   // 80 KB

typedef __nv_bfloat16 bf16;

// ---------------------------------------------------------------------------
// Device-global scratch (allocation-free rule)
// ---------------------------------------------------------------------------
__device__ bf16 g_xh[MS * D_], g_xl[MS * D_];
__device__ bf16 g_Wth[3][D_ * D_], g_Wtl[3][D_ * D_];        // W^T [n][k]
__device__ bf16 g_Qh[MS * D_], g_Ql[MS * D_];
__device__ bf16 g_Kh[MS * D_], g_Kl[MS * D_];
__device__ bf16 g_Vh[MS * D_], g_Vl[MS * D_];
__device__ bf16 g_Vth[MS * D_], g_Vtl[MS * D_];              // V^T [b][d][t]
__device__ float g_S[(size_t)B_ * S_ * S_];
__device__ bf16 g_Ph[(size_t)B_ * S_ * S_], g_Pl[(size_t)B_ * S_ * S_];

// ---------------------------------------------------------------------------
// Helpers
// ---------------------------------------------------------------------------
__device__ __forceinline__ void split1(float v, bf16& h, bf16& l) {
    h = __float2bfloat16_rn(v);
    l = __float2bfloat16_rn(v - __bfloat162float(h));
}

// byte offset of 16B chunk (row, chunk) inside a 128x16 bf16 array, xor swizzle
__device__ __forceinline__ uint32_t swzb(int row, int chunk) {
    return (uint32_t)((row * 2 + (chunk ^ ((row >> 2) & 1))) * 16);
}

__device__ __forceinline__ void ldsm4(uint32_t r[4], uint32_t a) {
    asm volatile("ldmatrix.sync.aligned.m8n8.x4.shared.b16 {%0,%1,%2,%3}, [%4];"
                 : "=r"(r[0]), "=r"(r[1]), "=r"(r[2]), "=r"(r[3]) : "r"(a));
}

__device__ __forceinline__ void mma_bf16(float c[4], const uint32_t a[4],
                                         const uint32_t b0, const uint32_t b1) {
    asm volatile(
        "mma.sync.aligned.m16n8k16.row.col.f32.bf16.bf16.f32 "
        "{%0,%1,%2,%3},{%4,%5,%6,%7},{%8,%9},{%0,%1,%2,%3};"
        : "+f"(c[0]), "+f"(c[1]), "+f"(c[2]), "+f"(c[3])
        : "r"(a[0]), "r"(a[1]), "r"(a[2]), "r"(a[3]), "r"(b0), "r"(b1));
}

__device__ __forceinline__ void cpasync16(uint32_t dst, const void* src) {
    asm volatile("cp.async.cg.shared.global [%0], [%1], 16;" :: "r"(dst), "l"(src));
}

// ---------------------------------------------------------------------------
// Stage loader: each of 256 threads copies one 16B chunk per operand array.
// thread t: row = t>>1, chunk = t&1
// ---------------------------------------------------------------------------
__device__ __forceinline__ void load_stage(uint32_t st,
        const bf16* __restrict__ Ah, const bf16* __restrict__ Al, int lda,
        const bf16* __restrict__ Bh, const bf16* __restrict__ Bl, int ldb,
        int bm, int bn, int koff, int cr, int cc, uint32_t so) {
    const size_t ao = (size_t)(bm + cr) * lda + koff + cc * 8;
    const size_t bo = (size_t)(bn + cr) * ldb + koff + cc * 8;
    cpasync16(st + so,             Ah + ao);
    cpasync16(st + ARR_B + so,     Al + ao);
    cpasync16(st + 2 * ARR_B + so, Bh + bo);
    cpasync16(st + 3 * ARR_B + so, Bl + bo);
    asm volatile("cp.async.commit_group;" ::: "memory");
}

// ---------------------------------------------------------------------------
// GEMM mainloop: C 128x128 block, A[m][k], B[n][k] as bf16 hi/lo pairs.
// acc += Ah*Bh + Al*Bh + Ah*Bl  (3-term schedule over NC = 3*KC k-chunks)
// 256 threads, 8 warps 2(m) x 4(n), warp tile 64x32. 5-stage cp.async ring.
// ---------------------------------------------------------------------------
__device__ void gemm_core(
    const bf16* __restrict__ Ahp, const bf16* __restrict__ Alp, int lda,
    const bf16* __restrict__ Bhp, const bf16* __restrict__ Blp, int ldb,
    int bm, int bn, int KC, float acc[4][4][4])
{
    extern __shared__ char dsm[];
    const uint32_t sb = (uint32_t)__cvta_generic_to_shared(dsm);

    const int tid = threadIdx.x, lane = tid & 31, warp = tid >> 5;
    const int wm = (warp >> 2) * 64, wn = (warp & 3) * 32;

    const int cr = tid >> 1, cc = tid & 1;
    const uint32_t so = swzb(cr, cc);

    // ldmatrix lane mappings (validated round 3)
    const int arow = (lane & 7) + 8 * ((lane >> 3) & 1);
    const int achk = lane >> 4;
    const int brow = (lane & 7) + 8 * ((lane >> 4) & 1);
    const int bchk = (lane >> 3) & 1;

    const int NC = 3 * KC;

    // prologue: 4 chunks (all term 0 — KC >= 4 always here)
#pragma unroll
    for (int i = 0; i < NSTG - 1; i++)
        load_stage(sb + i * STAGE_B, Ahp, Alp, lda, Bhp, Blp, ldb,
                   bm, bn, i * BK, cr, cc, so);

    int s = 0;
    for (int i = 0; i < NC; i++) {
        asm volatile("cp.async.wait_group %0;" :: "n"(NSTG - 2) : "memory");
        __syncthreads();

        // issue loads for chunk i+4 into stage (s+4)%5
        const int j = i + NSTG - 1;
        if (j < NC) {
            int ss = s + NSTG - 1; if (ss >= NSTG) ss -= NSTG;
            const int term = j / KC;
            const int kc = j - term * KC;
            const bf16* Ag = (term == 1) ? Alp : Ahp;
            const bf16* Bg = (term == 2) ? Blp : Bhp;
            // hi/lo both loaded but only needed pair used; load the pair into
            // the (Ah,Bh) slots of the stage; mma below always reads slots 0,2.
            const size_t ao = (size_t)(bm + cr) * lda + kc * BK + cc * 8;
            const size_t bo = (size_t)(bn + cr) * ldb + kc * BK + cc * 8;
            const uint32_t st = sb + ss * STAGE_B;
            cpasync16(st + so,             Ag + ao);
            cpasync16(st + 2 * ARR_B + so, Bg + bo);
        }
        asm volatile("cp.async.commit_group;" ::: "memory");

        // consume stage s: which operand slots hold this chunk's data?
        const uint32_t st = sb + s * STAGE_B;
        const bool pro = (i < NSTG - 1);   // prologue stages filled all 4 slots
        const int term = i / KC;
        // prologue chunks are term 0 (Ah,Bh) in slots (0,2) and also have
        // (Al,Bl) in slots (1,3) — but mainloop-refilled stages only have
        // slots (0,2) valid. Term selection already baked into the load.
        (void)pro; (void)term;

        uint32_t a[4][4], b[2][4];
#pragma unroll
        for (int ii = 0; ii < 4; ii++)
            ldsm4(a[ii], st + swzb(wm + 16 * ii + arow, achk));
#pragma unroll
        for (int p = 0; p < 2; p++)
            ldsm4(b[p], st + 2 * ARR_B + swzb(wn + 16 * p + brow, bchk));

#pragma unroll
        for (int ii = 0; ii < 4; ii++)
#pragma unroll
            for (int jj = 0; jj < 4; jj++) {
                const int p = jj >> 1, q = (jj & 1) * 2;
                mma_bf16(acc[ii][jj], a[ii], b[p][q], b[p][q + 1]);
            }

        if (++s == NSTG) s = 0;
    }
}

// NOTE on prologue: the first NSTG-1 stages are loaded with all 4 slots via
// load_stage (4 cp.asyncs), but consumption only reads slots 0 and 2 (Ah,Bh),
// which is exactly term 0. Correct, slightly redundant traffic on 4 chunks.

// ---------------------------------------------------------------------------
// Conversion kernels (unchanged)
// ---------------------------------------------------------------------------
__global__ void convert_x_kernel(const float* __restrict__ x) {
    size_t i = ((size_t)blockIdx.x * 256 + threadIdx.x) * 4;
    float4 v = *(const float4*)(x + i);
    bf16 h0, l0, h1, l1, h2, l2, h3, l3;
    split1(v.x, h0, l0); split1(v.y, h1, l1);
    split1(v.z, h2, l2); split1(v.w, h3, l3);
    *(__nv_bfloat162*)(g_xh + i)     = __halves2bfloat162(h0, h1);
    *(__nv_bfloat162*)(g_xh + i + 2) = __halves2bfloat162(h2, h3);
    *(__nv_bfloat162*)(g_xl + i)     = __halves2bfloat162(l0, l1);
    *(__nv_bfloat162*)(g_xl + i + 2) = __halves2bfloat162(l2, l3);
}

__global__ void convert_Wt_kernel(const float* __restrict__ Wq,
                                  const float* __restrict__ Wk,
                                  const float* __restrict__ Wv) {
    const float* W = blockIdx.z == 0 ? Wq : blockIdx.z == 1 ? Wk : Wv;
    bf16* Oh = g_Wth[blockIdx.z];
    bf16* Ol = g_Wtl[blockIdx.z];
    __shared__ float t[32][33];
    const int k0 = blockIdx.y * 32, n0 = blockIdx.x * 32;
    const int tx = threadIdx.x, ty = threadIdx.y;
#pragma unroll
    for (int r = 0; r < 32; r += 8)
        t[ty + r][tx] = W[(size_t)(k0 + ty + r) * D_ + n0 + tx];
    __syncthreads();
#pragma unroll
    for (int r = 0; r < 32; r += 8) {
        float v = t[tx][ty + r];
        bf16 h, l; split1(v, h, l);
        size_t o = (size_t)(n0 + ty + r) * D_ + k0 + tx;
        Oh[o] = h; Ol[o] = l;
    }
}

__global__ void transpose_V_kernel() {
    __shared__ bf16 th[32][33], tl[32][33];
    const int b = blockIdx.z;
    const int t0 = blockIdx.x * 32, d0 = blockIdx.y * 32;
    const int tx = threadIdx.x, ty = threadIdx.y;
    const bf16* Vh = g_Vh + (size_t)b * S_ * D_;
    const bf16* Vl = g_Vl + (size_t)b * S_ * D_;
#pragma unroll
    for (int r = 0; r < 32; r += 8) {
        size_t o = (size_t)(t0 + ty + r) * D_ + d0 + tx;
        th[ty + r][tx] = Vh[o];
        tl[ty + r][tx] = Vl[o];
    }
    __syncthreads();
    bf16* Oth = g_Vth + (size_t)b * D_ * S_;
    bf16* Otl = g_Vtl + (size_t)b * D_ * S_;
#pragma unroll
    for (int r = 0; r < 32; r += 8) {
        size_t o = (size_t)(d0 + ty + r) * S_ + t0 + tx;
        Oth[o] = th[tx][ty + r];
        Otl[o] = tl[tx][ty + r];
    }
}

// ---------------------------------------------------------------------------
// GEMM 1: QKV projection
// ---------------------------------------------------------------------------
__global__ __launch_bounds__(256, 1) void gemm_proj_kernel(
    const float* __restrict__ bqp, const float* __restrict__ bkp,
    const float* __restrict__ bvp) {
    const int z = blockIdx.z;
    const float* bias = z == 0 ? bqp : z == 1 ? bkp : bvp;
    bf16* Ch = z == 0 ? g_Qh : z == 1 ? g_Kh : g_Vh;
    bf16* Cl = z == 0 ? g_Ql : z == 1 ? g_Kl : g_Vl;
    const int bm = blockIdx.y * 128, bn = blockIdx.x * 128;

    float acc[4][4][4] = {};
    gemm_core(g_xh, g_xl, D_, g_Wth[z], g_Wtl[z], D_, bm, bn, D_ / BK, acc);

    const int lane = threadIdx.x & 31, warp = threadIdx.x >> 5;
    const int wm = (warp >> 2) * 64, wn = (warp & 3) * 32;
    const int g = lane >> 2, t = lane & 3;
#pragma unroll
    for (int i = 0; i < 4; i++)
#pragma unroll
        for (int j = 0; j < 4; j++) {
            const int col = bn + wn + 8 * j + 2 * t;
            const float b0 = bias[col], b1 = bias[col + 1];
            const int r0 = bm + wm + 16 * i + g;
            bf16 h0, l0, h1, l1;
            split1(acc[i][j][0] + b0, h0, l0);
            split1(acc[i][j][1] + b1, h1, l1);
            *(__nv_bfloat162*)(Ch + (size_t)r0 * D_ + col) = __halves2bfloat162(h0, h1);
            *(__nv_bfloat162*)(Cl + (size_t)r0 * D_ + col) = __halves2bfloat162(l0, l1);
            split1(acc[i][j][2] + b0, h0, l0);
            split1(acc[i][j][3] + b1, h1, l1);
            *(__nv_bfloat162*)(Ch + (size_t)(r0 + 8) * D_ + col) = __halves2bfloat162(h0, h1);
            *(__nv_bfloat162*)(Cl + (size_t)(r0 + 8) * D_ + col) = __halves2bfloat162(l0, l1);
        }
}

// ---------------------------------------------------------------------------
// GEMM 2: scores = (Q @ K^T) * scale
// ---------------------------------------------------------------------------
__global__ __launch_bounds__(256, 1) void gemm_scores_kernel() {
    const int b = blockIdx.z;
    const size_t off = (size_t)b * S_ * D_;
    const int bm = blockIdx.y * 128, bn = blockIdx.x * 128;

    float acc[4][4][4] = {};
    gemm_core(g_Qh + off, g_Ql + off, D_, g_Kh + off, g_Kl + off, D_,
              bm, bn, D_ / BK, acc);

    float* C = g_S + (size_t)b * S_ * S_;
    const int lane = threadIdx.x & 31, warp = threadIdx.x >> 5;
    const int wm = (warp >> 2) * 64, wn = (warp & 3) * 32;
    const int g = lane >> 2, t = lane & 3;
    const float sc = 0.03125f;
#pragma unroll
    for (int i = 0; i < 4; i++)
#pragma unroll
        for (int j = 0; j < 4; j++) {
            const int col = bn + wn + 8 * j + 2 * t;
            const int r0 = bm + wm + 16 * i + g;
            *(float2*)(C + (size_t)r0 * S_ + col) =
                make_float2(acc[i][j][0] * sc, acc[i][j][1] * sc);
            *(float2*)(C + (size_t)(r0 + 8) * S_ + col) =
                make_float2(acc[i][j][2] * sc, acc[i][j][3] * sc);
        }
}

// ---------------------------------------------------------------------------
// Softmax: fp32 scores -> attn bf16 hi/lo
// ---------------------------------------------------------------------------
__global__ __launch_bounds__(256) void softmax_kernel() {
    const size_t row = blockIdx.x;
    const float* p = g_S + row * (size_t)S_;
    bf16* oh = g_Ph + row * (size_t)S_;
    bf16* ol = g_Pl + row * (size_t)S_;
    const int tid = threadIdx.x;

    __shared__ float red[256];

    float v[8];
    float m = -INFINITY;
#pragma unroll
    for (int i = 0; i < 8; i++) {
        v[i] = p[tid + i * 256];
        m = fmaxf(m, v[i]);
    }
    red[tid] = m;
    __syncthreads();
    for (int s = 128; s > 0; s >>= 1) {
        if (tid < s) red[tid] = fmaxf(red[tid], red[tid + s]);
        __syncthreads();
    }
    m = red[0];
    __syncthreads();

    float sum = 0.f;
#pragma unroll
    for (int i = 0; i < 8; i++) {
        v[i] = __expf(v[i] - m);
        sum += v[i];
    }
    red[tid] = sum;
    __syncthreads();
    for (int s = 128; s > 0; s >>= 1) {
        if (tid < s) red[tid] += red[tid + s];
        __syncthreads();
    }
    const float inv = 1.0f / red[0];
#pragma unroll
    for (int i = 0; i < 8; i++) {
        bf16 h, l;
        split1(v[i] * inv, h, l);
        oh[tid + i * 256] = h;
        ol[tid + i * 256] = l;
    }
}

// ---------------------------------------------------------------------------
// GEMM 3: out = attn @ V
// ---------------------------------------------------------------------------
__global__ __launch_bounds__(256, 1) void gemm_av_kernel(float* __restrict__ out) {
    const int b = blockIdx.z;
    const bf16* Ah = g_Ph + (size_t)b * S_ * S_;
    const bf16* Al = g_Pl + (size_t)b * S_ * S_;
    const bf16* Bh = g_Vth + (size_t)b * D_ * S_;
    const bf16* Bl = g_Vtl + (size_t)b * D_ * S_;
    const int bm = blockIdx.y * 128, bn = blockIdx.x * 128;

    float acc[4][4][4] = {};
    gemm_core(Ah, Al, S_, Bh, Bl, S_, bm, bn, S_ / BK, acc);

    float* C = out + (size_t)b * S_ * D_;
    const int lane = threadIdx.x & 31, warp = threadIdx.x >> 5;
    const int wm = (warp >> 2) * 64, wn = (warp & 3) * 32;
    const int g = lane >> 2, t = lane & 3;
#pragma unroll
    for (int i = 0; i < 4; i++)
#pragma unroll
        for (int j = 0; j < 4; j++) {
            const int col = bn + wn + 8 * j + 2 * t;
            const int r0 = bm + wm + 16 * i + g;
            *(float2*)(C + (size_t)r0 * D_ + col) =
                make_float2(acc[i][j][0], acc[i][j][1]);
            *(float2*)(C + (size_t)(r0 + 8) * D_ + col) =
                make_float2(acc[i][j][2], acc[i][j][3]);
        }
}

// ---------------------------------------------------------------------------
// Launch
// ---------------------------------------------------------------------------
extern "C" void kernel_launch(void* const* d_in, const int* in_sizes, int n_in,
                              void* d_out, int out_size) {
    const float* x  = (const float*)d_in[0];
    const float* Wq = (const float*)d_in[1];
    const float* bq = (const float*)d_in[2];
    const float* Wk = (const float*)d_in[3];
    const float* bk = (const float*)d_in[4];
    const float* Wv = (const float*)d_in[5];
    const float* bv = (const float*)d_in[6];
    float* out = (float*)d_out;

    cudaFuncSetAttribute(gemm_proj_kernel,
                         cudaFuncAttributeMaxDynamicSharedMemorySize, SMEM_DYN);
    cudaFuncSetAttribute(gemm_scores_kernel,
                         cudaFuncAttributeMaxDynamicSharedMemorySize, SMEM_DYN);
    cudaFuncSetAttribute(gemm_av_kernel,
                         cudaFuncAttributeMaxDynamicSharedMemorySize, SMEM_DYN);

    convert_x_kernel<<<(MS * D_) / 1024, 256>>>(x);
    convert_Wt_kernel<<<dim3(32, 32, 3), dim3(32, 8)>>>(Wq, Wk, Wv);

    gemm_proj_kernel<<<dim3(D_ / 128, MS / 128, 3), 256, SMEM_DYN>>>(bq, bk, bv);

    transpose_V_kernel<<<dim3(S_ / 32, D_ / 32, B_), dim3(32, 8)>>>();

    gemm_scores_kernel<<<dim3(S_ / 128, S_ / 128, B_), 256, SMEM_DYN>>>();

    softmax_kernel<<<B_ * S_, 256>>>();

    gemm_av_kernel<<<dim3(D_ / 128, S_ / 128, B_), 256, SMEM_DYN>>>(out);
}

// round 6
// speedup vs baseline: 2.3664x; 1.0423x over previous
#include <cuda_runtime.h>
#include <cuda_bf16.h>
#include <stdint.h>
#include <math.h>

#define B_  4
#define S_  2048
#define D_  1024
#define MS  (B_*S_)
#define BK  16
#define NSTG 4
#define A_ARR 4096                     // 128 rows x 16 bf16 x 2B
#define B_ARR 8192                     // 256 rows x 16 bf16 x 2B
#define OFF_AL (A_ARR)
#define OFF_BH (2*A_ARR)
#define OFF_BL (2*A_ARR + B_ARR)
#define STAGE_B (2*A_ARR + 2*B_ARR)    // 24 KB
#define SMEM_DYN (NSTG*STAGE_B)        // 96 KB

typedef __nv_bfloat16 bf16;

// ---------------------------------------------------------------------------
// Device-global scratch
// ---------------------------------------------------------------------------
__device__ bf16 g_xh[MS * D_], g_xl[MS * D_];
__device__ bf16 g_Wth[3][D_ * D_], g_Wtl[3][D_ * D_];        // W^T [n][k]
__device__ bf16 g_Qh[MS * D_], g_Ql[MS * D_];
__device__ bf16 g_Kh[MS * D_], g_Kl[MS * D_];
__device__ bf16 g_Vh[MS * D_], g_Vl[MS * D_];
__device__ bf16 g_Vth[MS * D_], g_Vtl[MS * D_];              // V^T [b][d][t]
__device__ float g_S[(size_t)B_ * S_ * S_];
__device__ bf16 g_Ph[(size_t)B_ * S_ * S_], g_Pl[(size_t)B_ * S_ * S_];

// ---------------------------------------------------------------------------
// Helpers
// ---------------------------------------------------------------------------
__device__ __forceinline__ void split1(float v, bf16& h, bf16& l) {
    h = __float2bfloat16_rn(v);
    l = __float2bfloat16_rn(v - __bfloat162float(h));
}

// byte offset of 16B chunk (row, chunk) in a [rows x 16 bf16] array, xor swizzle
__device__ __forceinline__ uint32_t swzb(int row, int chunk) {
    return (uint32_t)((row * 2 + (chunk ^ ((row >> 2) & 1))) * 16);
}

__device__ __forceinline__ void ldsm4(uint32_t r[4], uint32_t a) {
    asm volatile("ldmatrix.sync.aligned.m8n8.x4.shared.b16 {%0,%1,%2,%3}, [%4];"
                 : "=r"(r[0]), "=r"(r[1]), "=r"(r[2]), "=r"(r[3]) : "r"(a));
}

__device__ __forceinline__ void mma_bf16(float c[4], const uint32_t a[4],
                                         const uint32_t b0, const uint32_t b1) {
    asm volatile(
        "mma.sync.aligned.m16n8k16.row.col.f32.bf16.bf16.f32 "
        "{%0,%1,%2,%3},{%4,%5,%6,%7},{%8,%9},{%0,%1,%2,%3};"
        : "+f"(c[0]), "+f"(c[1]), "+f"(c[2]), "+f"(c[3])
        : "r"(a[0]), "r"(a[1]), "r"(a[2]), "r"(a[3]), "r"(b0), "r"(b1));
}

__device__ __forceinline__ void cpasync16(uint32_t dst, const void* src) {
    asm volatile("cp.async.cg.shared.global [%0], [%1], 16;" :: "r"(dst), "l"(src));
}

// ---------------------------------------------------------------------------
// Stage loader: A 128x16 hi/lo + B 256x16 hi/lo, 6 cp.asyncs per thread
// ---------------------------------------------------------------------------
__device__ __forceinline__ void load_stage(uint32_t st,
        const bf16* __restrict__ Ah, const bf16* __restrict__ Al, int lda,
        const bf16* __restrict__ Bh, const bf16* __restrict__ Bl, int ldb,
        int bm, int bn, int koff, int tid) {
    const int cr = tid >> 1, cc = tid & 1;
    const uint32_t so = swzb(cr, cc);
    const size_t ao = (size_t)(bm + cr) * lda + koff + cc * 8;
    cpasync16(st + so,          Ah + ao);
    cpasync16(st + OFF_AL + so, Al + ao);
    const size_t bo = (size_t)(bn + cr) * ldb + koff + cc * 8;
    cpasync16(st + OFF_BH + so, Bh + bo);
    cpasync16(st + OFF_BL + so, Bl + bo);
    const uint32_t so2 = swzb(cr + 128, cc);
    const size_t bo2 = (size_t)(bn + cr + 128) * ldb + koff + cc * 8;
    cpasync16(st + OFF_BH + so2, Bh + bo2);
    cpasync16(st + OFF_BL + so2, Bl + bo2);
    asm volatile("cp.async.commit_group;" ::: "memory");
}

// ---------------------------------------------------------------------------
// GEMM mainloop: C 128x256 block, A[m][k], B[n][k] as bf16 hi/lo pairs.
// acc += Ah*Bh + Ah*Bl + Al*Bh with register fragment reuse (96 MMA/warp/chunk)
// 256 threads, 8 warps 2(m) x 4(n), warp tile 64x64. 4-stage cp.async ring.
// ---------------------------------------------------------------------------
__device__ void gemm_core(
    const bf16* __restrict__ Ahp, const bf16* __restrict__ Alp, int lda,
    const bf16* __restrict__ Bhp, const bf16* __restrict__ Blp, int ldb,
    int bm, int bn, int KC, float acc[4][8][4])
{
    extern __shared__ char dsm[];
    const uint32_t sb = (uint32_t)__cvta_generic_to_shared(dsm);

    const int tid = threadIdx.x, lane = tid & 31, warp = tid >> 5;
    const int wm = (warp >> 2) * 64, wn = (warp & 3) * 64;

    // ldmatrix lane mappings (validated rounds 3/5)
    const int arow = (lane & 7) + 8 * ((lane >> 3) & 1);
    const int achk = lane >> 4;
    const int brow = (lane & 7) + 8 * ((lane >> 4) & 1);
    const int bchk = (lane >> 3) & 1;

    // prologue
#pragma unroll
    for (int i = 0; i < NSTG - 1; i++)
        load_stage(sb + i * STAGE_B, Ahp, Alp, lda, Bhp, Blp, ldb,
                   bm, bn, i * BK, tid);

    int s = 0;
    for (int kt = 0; kt < KC; kt++) {
        asm volatile("cp.async.wait_group %0;" :: "n"(NSTG - 2) : "memory");
        __syncthreads();

        const int j = kt + NSTG - 1;
        if (j < KC) {
            int ss = s + NSTG - 1; if (ss >= NSTG) ss -= NSTG;
            load_stage(sb + ss * STAGE_B, Ahp, Alp, lda, Bhp, Blp, ldb,
                       bm, bn, j * BK, tid);
        } else {
            asm volatile("cp.async.commit_group;" ::: "memory");
        }

        const uint32_t st = sb + s * STAGE_B;

        uint32_t ah[4][4], al[4][4], bh[4][4], bl[4][4];
#pragma unroll
        for (int i = 0; i < 4; i++) {
            const uint32_t o = swzb(wm + 16 * i + arow, achk);
            ldsm4(ah[i], st + o);
            ldsm4(al[i], st + OFF_AL + o);
        }
#pragma unroll
        for (int p = 0; p < 4; p++) {
            const uint32_t o = swzb(wn + 16 * p + brow, bchk);
            ldsm4(bh[p], st + OFF_BH + o);
            ldsm4(bl[p], st + OFF_BL + o);
        }

#pragma unroll
        for (int i = 0; i < 4; i++)
#pragma unroll
            for (int jj = 0; jj < 8; jj++) {
                const int p = jj >> 1, q = (jj & 1) * 2;
                mma_bf16(acc[i][jj], ah[i], bh[p][q], bh[p][q + 1]);
                mma_bf16(acc[i][jj], ah[i], bl[p][q], bl[p][q + 1]);
                mma_bf16(acc[i][jj], al[i], bh[p][q], bh[p][q + 1]);
            }

        if (++s == NSTG) s = 0;
    }
}

// ---------------------------------------------------------------------------
// Conversion kernels (unchanged)
// ---------------------------------------------------------------------------
__global__ void convert_x_kernel(const float* __restrict__ x) {
    size_t i = ((size_t)blockIdx.x * 256 + threadIdx.x) * 4;
    float4 v = *(const float4*)(x + i);
    bf16 h0, l0, h1, l1, h2, l2, h3, l3;
    split1(v.x, h0, l0); split1(v.y, h1, l1);
    split1(v.z, h2, l2); split1(v.w, h3, l3);
    *(__nv_bfloat162*)(g_xh + i)     = __halves2bfloat162(h0, h1);
    *(__nv_bfloat162*)(g_xh + i + 2) = __halves2bfloat162(h2, h3);
    *(__nv_bfloat162*)(g_xl + i)     = __halves2bfloat162(l0, l1);
    *(__nv_bfloat162*)(g_xl + i + 2) = __halves2bfloat162(l2, l3);
}

__global__ void convert_Wt_kernel(const float* __restrict__ Wq,
                                  const float* __restrict__ Wk,
                                  const float* __restrict__ Wv) {
    const float* W = blockIdx.z == 0 ? Wq : blockIdx.z == 1 ? Wk : Wv;
    bf16* Oh = g_Wth[blockIdx.z];
    bf16* Ol = g_Wtl[blockIdx.z];
    __shared__ float t[32][33];
    const int k0 = blockIdx.y * 32, n0 = blockIdx.x * 32;
    const int tx = threadIdx.x, ty = threadIdx.y;
#pragma unroll
    for (int r = 0; r < 32; r += 8)
        t[ty + r][tx] = W[(size_t)(k0 + ty + r) * D_ + n0 + tx];
    __syncthreads();
#pragma unroll
    for (int r = 0; r < 32; r += 8) {
        float v = t[tx][ty + r];
        bf16 h, l; split1(v, h, l);
        size_t o = (size_t)(n0 + ty + r) * D_ + k0 + tx;
        Oh[o] = h; Ol[o] = l;
    }
}

__global__ void transpose_V_kernel() {
    __shared__ bf16 th[32][33], tl[32][33];
    const int b = blockIdx.z;
    const int t0 = blockIdx.x * 32, d0 = blockIdx.y * 32;
    const int tx = threadIdx.x, ty = threadIdx.y;
    const bf16* Vh = g_Vh + (size_t)b * S_ * D_;
    const bf16* Vl = g_Vl + (size_t)b * S_ * D_;
#pragma unroll
    for (int r = 0; r < 32; r += 8) {
        size_t o = (size_t)(t0 + ty + r) * D_ + d0 + tx;
        th[ty + r][tx] = Vh[o];
        tl[ty + r][tx] = Vl[o];
    }
    __syncthreads();
    bf16* Oth = g_Vth + (size_t)b * D_ * S_;
    bf16* Otl = g_Vtl + (size_t)b * D_ * S_;
#pragma unroll
    for (int r = 0; r < 32; r += 8) {
        size_t o = (size_t)(d0 + ty + r) * S_ + t0 + tx;
        Oth[o] = th[tx][ty + r];
        Otl[o] = tl[tx][ty + r];
    }
}

// ---------------------------------------------------------------------------
// GEMM 1: QKV projection
// ---------------------------------------------------------------------------
__global__ __launch_bounds__(256, 1) void gemm_proj_kernel(
    const float* __restrict__ bqp, const float* __restrict__ bkp,
    const float* __restrict__ bvp) {
    const int z = blockIdx.z;
    const float* bias = z == 0 ? bqp : z == 1 ? bkp : bvp;
    bf16* Ch = z == 0 ? g_Qh : z == 1 ? g_Kh : g_Vh;
    bf16* Cl = z == 0 ? g_Ql : z == 1 ? g_Kl : g_Vl;
    const int bm = blockIdx.y * 128, bn = blockIdx.x * 256;

    float acc[4][8][4] = {};
    gemm_core(g_xh, g_xl, D_, g_Wth[z], g_Wtl[z], D_, bm, bn, D_ / BK, acc);

    const int lane = threadIdx.x & 31, warp = threadIdx.x >> 5;
    const int wm = (warp >> 2) * 64, wn = (warp & 3) * 64;
    const int g = lane >> 2, t = lane & 3;
#pragma unroll
    for (int i = 0; i < 4; i++)
#pragma unroll
        for (int j = 0; j < 8; j++) {
            const int col = bn + wn + 8 * j + 2 * t;
            const float b0 = bias[col], b1 = bias[col + 1];
            const int r0 = bm + wm + 16 * i + g;
            bf16 h0, l0, h1, l1;
            split1(acc[i][j][0] + b0, h0, l0);
            split1(acc[i][j][1] + b1, h1, l1);
            *(__nv_bfloat162*)(Ch + (size_t)r0 * D_ + col) = __halves2bfloat162(h0, h1);
            *(__nv_bfloat162*)(Cl + (size_t)r0 * D_ + col) = __halves2bfloat162(l0, l1);
            split1(acc[i][j][2] + b0, h0, l0);
            split1(acc[i][j][3] + b1, h1, l1);
            *(__nv_bfloat162*)(Ch + (size_t)(r0 + 8) * D_ + col) = __halves2bfloat162(h0, h1);
            *(__nv_bfloat162*)(Cl + (size_t)(r0 + 8) * D_ + col) = __halves2bfloat162(l0, l1);
        }
}

// ---------------------------------------------------------------------------
// GEMM 2: scores = (Q @ K^T) * scale
// ---------------------------------------------------------------------------
__global__ __launch_bounds__(256, 1) void gemm_scores_kernel() {
    const int b = blockIdx.z;
    const size_t off = (size_t)b * S_ * D_;
    const int bm = blockIdx.y * 128, bn = blockIdx.x * 256;

    float acc[4][8][4] = {};
    gemm_core(g_Qh + off, g_Ql + off, D_, g_Kh + off, g_Kl + off, D_,
              bm, bn, D_ / BK, acc);

    float* C = g_S + (size_t)b * S_ * S_;
    const int lane = threadIdx.x & 31, warp = threadIdx.x >> 5;
    const int wm = (warp >> 2) * 64, wn = (warp & 3) * 64;
    const int g = lane >> 2, t = lane & 3;
    const float sc = 0.03125f;
#pragma unroll
    for (int i = 0; i < 4; i++)
#pragma unroll
        for (int j = 0; j < 8; j++) {
            const int col = bn + wn + 8 * j + 2 * t;
            const int r0 = bm + wm + 16 * i + g;
            *(float2*)(C + (size_t)r0 * S_ + col) =
                make_float2(acc[i][j][0] * sc, acc[i][j][1] * sc);
            *(float2*)(C + (size_t)(r0 + 8) * S_ + col) =
                make_float2(acc[i][j][2] * sc, acc[i][j][3] * sc);
        }
}

// ---------------------------------------------------------------------------
// Softmax: fp32 scores -> attn bf16 hi/lo
// ---------------------------------------------------------------------------
__global__ __launch_bounds__(256) void softmax_kernel() {
    const size_t row = blockIdx.x;
    const float* p = g_S + row * (size_t)S_;
    bf16* oh = g_Ph + row * (size_t)S_;
    bf16* ol = g_Pl + row * (size_t)S_;
    const int tid = threadIdx.x;

    __shared__ float red[256];

    float v[8];
    float m = -INFINITY;
#pragma unroll
    for (int i = 0; i < 8; i++) {
        v[i] = p[tid + i * 256];
        m = fmaxf(m, v[i]);
    }
    red[tid] = m;
    __syncthreads();
    for (int s = 128; s > 0; s >>= 1) {
        if (tid < s) red[tid] = fmaxf(red[tid], red[tid + s]);
        __syncthreads();
    }
    m = red[0];
    __syncthreads();

    float sum = 0.f;
#pragma unroll
    for (int i = 0; i < 8; i++) {
        v[i] = __expf(v[i] - m);
        sum += v[i];
    }
    red[tid] = sum;
    __syncthreads();
    for (int s = 128; s > 0; s >>= 1) {
        if (tid < s) red[tid] += red[tid + s];
        __syncthreads();
    }
    const float inv = 1.0f / red[0];
#pragma unroll
    for (int i = 0; i < 8; i++) {
        bf16 h, l;
        split1(v[i] * inv, h, l);
        oh[tid + i * 256] = h;
        ol[tid + i * 256] = l;
    }
}

// ---------------------------------------------------------------------------
// GEMM 3: out = attn @ V
// ---------------------------------------------------------------------------
__global__ __launch_bounds__(256, 1) void gemm_av_kernel(float* __restrict__ out) {
    const int b = blockIdx.z;
    const bf16* Ah = g_Ph + (size_t)b * S_ * S_;
    const bf16* Al = g_Pl + (size_t)b * S_ * S_;
    const bf16* Bh = g_Vth + (size_t)b * D_ * S_;
    const bf16* Bl = g_Vtl + (size_t)b * D_ * S_;
    const int bm = blockIdx.y * 128, bn = blockIdx.x * 256;

    float acc[4][8][4] = {};
    gemm_core(Ah, Al, S_, Bh, Bl, S_, bm, bn, S_ / BK, acc);

    float* C = out + (size_t)b * S_ * D_;
    const int lane = threadIdx.x & 31, warp = threadIdx.x >> 5;
    const int wm = (warp >> 2) * 64, wn = (warp & 3) * 64;
    const int g = lane >> 2, t = lane & 3;
#pragma unroll
    for (int i = 0; i < 4; i++)
#pragma unroll
        for (int j = 0; j < 8; j++) {
            const int col = bn + wn + 8 * j + 2 * t;
            const int r0 = bm + wm + 16 * i + g;
            *(float2*)(C + (size_t)r0 * D_ + col) =
                make_float2(acc[i][j][0], acc[i][j][1]);
            *(float2*)(C + (size_t)(r0 + 8) * D_ + col) =
                make_float2(acc[i][j][2], acc[i][j][3]);
        }
}

// ---------------------------------------------------------------------------
// Launch
// ---------------------------------------------------------------------------
extern "C" void kernel_launch(void* const* d_in, const int* in_sizes, int n_in,
                              void* d_out, int out_size) {
    const float* x  = (const float*)d_in[0];
    const float* Wq = (const float*)d_in[1];
    const float* bq = (const float*)d_in[2];
    const float* Wk = (const float*)d_in[3];
    const float* bk = (const float*)d_in[4];
    const float* Wv = (const float*)d_in[5];
    const float* bv = (const float*)d_in[6];
    float* out = (float*)d_out;

    cudaFuncSetAttribute(gemm_proj_kernel,
                         cudaFuncAttributeMaxDynamicSharedMemorySize, SMEM_DYN);
    cudaFuncSetAttribute(gemm_scores_kernel,
                         cudaFuncAttributeMaxDynamicSharedMemorySize, SMEM_DYN);
    cudaFuncSetAttribute(gemm_av_kernel,
                         cudaFuncAttributeMaxDynamicSharedMemorySize, SMEM_DYN);

    convert_x_kernel<<<(MS * D_) / 1024, 256>>>(x);
    convert_Wt_kernel<<<dim3(32, 32, 3), dim3(32, 8)>>>(Wq, Wk, Wv);

    gemm_proj_kernel<<<dim3(D_ / 256, MS / 128, 3), 256, SMEM_DYN>>>(bq, bk, bv);

    transpose_V_kernel<<<dim3(S_ / 32, D_ / 32, B_), dim3(32, 8)>>>();

    gemm_scores_kernel<<<dim3(S_ / 256, S_ / 128, B_), 256, SMEM_DYN>>>();

    softmax_kernel<<<B_ * S_, 256>>>();

    gemm_av_kernel<<<dim3(D_ / 256, S_ / 128, B_), 256, SMEM_DYN>>>(out);
}

// round 7
// speedup vs baseline: 2.3780x; 1.0049x over previous
#include <cuda_runtime.h>
#include <cuda_bf16.h>
#include <stdint.h>
#include <math.h>

#define B_  4
#define S_  2048
#define D_  1024
#define MS  (B_*S_)
#define BK  16
#define NSTG 4
#define A_ARR 4096                     // 128 rows x 16 bf16 x 2B
#define B_ARR 8192                     // 256 rows x 16 bf16 x 2B
#define OFF_AL (A_ARR)
#define OFF_BH (2*A_ARR)
#define OFF_BL (2*A_ARR + B_ARR)
#define STAGE_B (2*A_ARR + 2*B_ARR)    // 24 KB
#define SMEM_DYN (NSTG*STAGE_B)        // 96 KB

typedef __nv_bfloat16 bf16;

// ---------------------------------------------------------------------------
// Device-global scratch
// ---------------------------------------------------------------------------
__device__ bf16 g_xh[MS * D_], g_xl[MS * D_];
__device__ bf16 g_Wth[3][D_ * D_], g_Wtl[3][D_ * D_];        // W^T [n][k]
__device__ bf16 g_Qh[MS * D_], g_Ql[MS * D_];
__device__ bf16 g_Kh[MS * D_], g_Kl[MS * D_];
__device__ bf16 g_Vh[MS * D_], g_Vl[MS * D_];
__device__ bf16 g_Vth[MS * D_], g_Vtl[MS * D_];              // V^T [b][d][t]
__device__ float g_S[(size_t)B_ * S_ * S_];
__device__ bf16 g_Ph[(size_t)B_ * S_ * S_], g_Pl[(size_t)B_ * S_ * S_];

// ---------------------------------------------------------------------------
// Helpers
// ---------------------------------------------------------------------------
__device__ __forceinline__ void split1(float v, bf16& h, bf16& l) {
    h = __float2bfloat16_rn(v);
    l = __float2bfloat16_rn(v - __bfloat162float(h));
}

// byte offset of 16B chunk (row, chunk) in a [rows x 16 bf16] array, xor swizzle
__device__ __forceinline__ uint32_t swzb(int row, int chunk) {
    return (uint32_t)((row * 2 + (chunk ^ ((row >> 2) & 1))) * 16);
}

__device__ __forceinline__ void ldsm4(uint32_t r[4], uint32_t a) {
    asm volatile("ldmatrix.sync.aligned.m8n8.x4.shared.b16 {%0,%1,%2,%3}, [%4];"
                 : "=r"(r[0]), "=r"(r[1]), "=r"(r[2]), "=r"(r[3]) : "r"(a));
}

__device__ __forceinline__ void mma_bf16(float c[4], const uint32_t a[4],
                                         const uint32_t b0, const uint32_t b1) {
    asm volatile(
        "mma.sync.aligned.m16n8k16.row.col.f32.bf16.bf16.f32 "
        "{%0,%1,%2,%3},{%4,%5,%6,%7},{%8,%9},{%0,%1,%2,%3};"
        : "+f"(c[0]), "+f"(c[1]), "+f"(c[2]), "+f"(c[3])
        : "r"(a[0]), "r"(a[1]), "r"(a[2]), "r"(a[3]), "r"(b0), "r"(b1));
}

__device__ __forceinline__ void cpasync16(uint32_t dst, const void* src) {
    asm volatile("cp.async.cg.shared.global [%0], [%1], 16;" :: "r"(dst), "l"(src));
}

// ---------------------------------------------------------------------------
// Stage loader: A 128x16 hi/lo + B 256x16 hi/lo, 6 cp.asyncs per thread
// ---------------------------------------------------------------------------
__device__ __forceinline__ void load_stage(uint32_t st,
        const bf16* __restrict__ Ah, const bf16* __restrict__ Al, int lda,
        const bf16* __restrict__ Bh, const bf16* __restrict__ Bl, int ldb,
        int bm, int bn, int koff, int tid) {
    const int cr = tid >> 1, cc = tid & 1;
    const uint32_t so = swzb(cr, cc);
    const size_t ao = (size_t)(bm + cr) * lda + koff + cc * 8;
    cpasync16(st + so,          Ah + ao);
    cpasync16(st + OFF_AL + so, Al + ao);
    const size_t bo = (size_t)(bn + cr) * ldb + koff + cc * 8;
    cpasync16(st + OFF_BH + so, Bh + bo);
    cpasync16(st + OFF_BL + so, Bl + bo);
    const uint32_t so2 = swzb(cr + 128, cc);
    const size_t bo2 = (size_t)(bn + cr + 128) * ldb + koff + cc * 8;
    cpasync16(st + OFF_BH + so2, Bh + bo2);
    cpasync16(st + OFF_BL + so2, Bl + bo2);
    asm volatile("cp.async.commit_group;" ::: "memory");
}

// ---------------------------------------------------------------------------
// GEMM mainloop: C 128x256 block, A[m][k], B[n][k] as bf16 hi/lo pairs.
// acc += Ah*Bh + Al*Bh + Ah*Bl, TERM-MAJOR instruction order so consecutive
// MMAs never share an accumulator (32 independent chains between reuses).
// 256 threads, 8 warps 2(m) x 4(n), warp tile 64x64. 4-stage cp.async ring.
// ---------------------------------------------------------------------------
__device__ void gemm_core(
    const bf16* __restrict__ Ahp, const bf16* __restrict__ Alp, int lda,
    const bf16* __restrict__ Bhp, const bf16* __restrict__ Blp, int ldb,
    int bm, int bn, int KC, float acc[4][8][4])
{
    extern __shared__ char dsm[];
    const uint32_t sb = (uint32_t)__cvta_generic_to_shared(dsm);

    const int tid = threadIdx.x, lane = tid & 31, warp = tid >> 5;
    const int wm = (warp >> 2) * 64, wn = (warp & 3) * 64;

    // ldmatrix lane mappings (validated rounds 3/5/6)
    const int arow = (lane & 7) + 8 * ((lane >> 3) & 1);
    const int achk = lane >> 4;
    const int brow = (lane & 7) + 8 * ((lane >> 4) & 1);
    const int bchk = (lane >> 3) & 1;

    // prologue
#pragma unroll
    for (int i = 0; i < NSTG - 1; i++)
        load_stage(sb + i * STAGE_B, Ahp, Alp, lda, Bhp, Blp, ldb,
                   bm, bn, i * BK, tid);

    int s = 0;
    for (int kt = 0; kt < KC; kt++) {
        asm volatile("cp.async.wait_group %0;" :: "n"(NSTG - 2) : "memory");
        __syncthreads();

        const int j = kt + NSTG - 1;
        if (j < KC) {
            int ss = s + NSTG - 1; if (ss >= NSTG) ss -= NSTG;
            load_stage(sb + ss * STAGE_B, Ahp, Alp, lda, Bhp, Blp, ldb,
                       bm, bn, j * BK, tid);
        } else {
            asm volatile("cp.async.commit_group;" ::: "memory");
        }

        const uint32_t st = sb + s * STAGE_B;

        uint32_t ah[4][4], al[4][4], bh[4][4], bl[4][4];
#pragma unroll
        for (int i = 0; i < 4; i++) {
            const uint32_t o = swzb(wm + 16 * i + arow, achk);
            ldsm4(ah[i], st + o);
            ldsm4(al[i], st + OFF_AL + o);
        }
#pragma unroll
        for (int p = 0; p < 4; p++) {
            const uint32_t o = swzb(wn + 16 * p + brow, bchk);
            ldsm4(bh[p], st + OFF_BH + o);
            ldsm4(bl[p], st + OFF_BL + o);
        }

        // term 0: Ah * Bh   (32 independent accumulators back-to-back)
#pragma unroll
        for (int i = 0; i < 4; i++)
#pragma unroll
            for (int jj = 0; jj < 8; jj++) {
                const int p = jj >> 1, q = (jj & 1) * 2;
                mma_bf16(acc[i][jj], ah[i], bh[p][q], bh[p][q + 1]);
            }
        // term 1: Al * Bh
#pragma unroll
        for (int i = 0; i < 4; i++)
#pragma unroll
            for (int jj = 0; jj < 8; jj++) {
                const int p = jj >> 1, q = (jj & 1) * 2;
                mma_bf16(acc[i][jj], al[i], bh[p][q], bh[p][q + 1]);
            }
        // term 2: Ah * Bl
#pragma unroll
        for (int i = 0; i < 4; i++)
#pragma unroll
            for (int jj = 0; jj < 8; jj++) {
                const int p = jj >> 1, q = (jj & 1) * 2;
                mma_bf16(acc[i][jj], ah[i], bl[p][q], bl[p][q + 1]);
            }

        if (++s == NSTG) s = 0;
    }
}

// ---------------------------------------------------------------------------
// Conversion kernels (unchanged)
// ---------------------------------------------------------------------------
__global__ void convert_x_kernel(const float* __restrict__ x) {
    size_t i = ((size_t)blockIdx.x * 256 + threadIdx.x) * 4;
    float4 v = *(const float4*)(x + i);
    bf16 h0, l0, h1, l1, h2, l2, h3, l3;
    split1(v.x, h0, l0); split1(v.y, h1, l1);
    split1(v.z, h2, l2); split1(v.w, h3, l3);
    *(__nv_bfloat162*)(g_xh + i)     = __halves2bfloat162(h0, h1);
    *(__nv_bfloat162*)(g_xh + i + 2) = __halves2bfloat162(h2, h3);
    *(__nv_bfloat162*)(g_xl + i)     = __halves2bfloat162(l0, l1);
    *(__nv_bfloat162*)(g_xl + i + 2) = __halves2bfloat162(l2, l3);
}

__global__ void convert_Wt_kernel(const float* __restrict__ Wq,
                                  const float* __restrict__ Wk,
                                  const float* __restrict__ Wv) {
    const float* W = blockIdx.z == 0 ? Wq : blockIdx.z == 1 ? Wk : Wv;
    bf16* Oh = g_Wth[blockIdx.z];
    bf16* Ol = g_Wtl[blockIdx.z];
    __shared__ float t[32][33];
    const int k0 = blockIdx.y * 32, n0 = blockIdx.x * 32;
    const int tx = threadIdx.x, ty = threadIdx.y;
#pragma unroll
    for (int r = 0; r < 32; r += 8)
        t[ty + r][tx] = W[(size_t)(k0 + ty + r) * D_ + n0 + tx];
    __syncthreads();
#pragma unroll
    for (int r = 0; r < 32; r += 8) {
        float v = t[tx][ty + r];
        bf16 h, l; split1(v, h, l);
        size_t o = (size_t)(n0 + ty + r) * D_ + k0 + tx;
        Oh[o] = h; Ol[o] = l;
    }
}

__global__ void transpose_V_kernel() {
    __shared__ bf16 th[32][33], tl[32][33];
    const int b = blockIdx.z;
    const int t0 = blockIdx.x * 32, d0 = blockIdx.y * 32;
    const int tx = threadIdx.x, ty = threadIdx.y;
    const bf16* Vh = g_Vh + (size_t)b * S_ * D_;
    const bf16* Vl = g_Vl + (size_t)b * S_ * D_;
#pragma unroll
    for (int r = 0; r < 32; r += 8) {
        size_t o = (size_t)(t0 + ty + r) * D_ + d0 + tx;
        th[ty + r][tx] = Vh[o];
        tl[ty + r][tx] = Vl[o];
    }
    __syncthreads();
    bf16* Oth = g_Vth + (size_t)b * D_ * S_;
    bf16* Otl = g_Vtl + (size_t)b * D_ * S_;
#pragma unroll
    for (int r = 0; r < 32; r += 8) {
        size_t o = (size_t)(d0 + ty + r) * S_ + t0 + tx;
        Oth[o] = th[tx][ty + r];
        Otl[o] = tl[tx][ty + r];
    }
}

// ---------------------------------------------------------------------------
// GEMM 1: QKV projection
// ---------------------------------------------------------------------------
__global__ __launch_bounds__(256, 1) void gemm_proj_kernel(
    const float* __restrict__ bqp, const float* __restrict__ bkp,
    const float* __restrict__ bvp) {
    const int z = blockIdx.z;
    const float* bias = z == 0 ? bqp : z == 1 ? bkp : bvp;
    bf16* Ch = z == 0 ? g_Qh : z == 1 ? g_Kh : g_Vh;
    bf16* Cl = z == 0 ? g_Ql : z == 1 ? g_Kl : g_Vl;
    const int bm = blockIdx.y * 128, bn = blockIdx.x * 256;

    float acc[4][8][4] = {};
    gemm_core(g_xh, g_xl, D_, g_Wth[z], g_Wtl[z], D_, bm, bn, D_ / BK, acc);

    const int lane = threadIdx.x & 31, warp = threadIdx.x >> 5;
    const int wm = (warp >> 2) * 64, wn = (warp & 3) * 64;
    const int g = lane >> 2, t = lane & 3;
#pragma unroll
    for (int i = 0; i < 4; i++)
#pragma unroll
        for (int j = 0; j < 8; j++) {
            const int col = bn + wn + 8 * j + 2 * t;
            const float b0 = bias[col], b1 = bias[col + 1];
            const int r0 = bm + wm + 16 * i + g;
            bf16 h0, l0, h1, l1;
            split1(acc[i][j][0] + b0, h0, l0);
            split1(acc[i][j][1] + b1, h1, l1);
            *(__nv_bfloat162*)(Ch + (size_t)r0 * D_ + col) = __halves2bfloat162(h0, h1);
            *(__nv_bfloat162*)(Cl + (size_t)r0 * D_ + col) = __halves2bfloat162(l0, l1);
            split1(acc[i][j][2] + b0, h0, l0);
            split1(acc[i][j][3] + b1, h1, l1);
            *(__nv_bfloat162*)(Ch + (size_t)(r0 + 8) * D_ + col) = __halves2bfloat162(h0, h1);
            *(__nv_bfloat162*)(Cl + (size_t)(r0 + 8) * D_ + col) = __halves2bfloat162(l0, l1);
        }
}

// ---------------------------------------------------------------------------
// GEMM 2: scores = (Q @ K^T) * scale
// ---------------------------------------------------------------------------
__global__ __launch_bounds__(256, 1) void gemm_scores_kernel() {
    const int b = blockIdx.z;
    const size_t off = (size_t)b * S_ * D_;
    const int bm = blockIdx.y * 128, bn = blockIdx.x * 256;

    float acc[4][8][4] = {};
    gemm_core(g_Qh + off, g_Ql + off, D_, g_Kh + off, g_Kl + off, D_,
              bm, bn, D_ / BK, acc);

    float* C = g_S + (size_t)b * S_ * S_;
    const int lane = threadIdx.x & 31, warp = threadIdx.x >> 5;
    const int wm = (warp >> 2) * 64, wn = (warp & 3) * 64;
    const int g = lane >> 2, t = lane & 3;
    const float sc = 0.03125f;
#pragma unroll
    for (int i = 0; i < 4; i++)
#pragma unroll
        for (int j = 0; j < 8; j++) {
            const int col = bn + wn + 8 * j + 2 * t;
            const int r0 = bm + wm + 16 * i + g;
            *(float2*)(C + (size_t)r0 * S_ + col) =
                make_float2(acc[i][j][0] * sc, acc[i][j][1] * sc);
            *(float2*)(C + (size_t)(r0 + 8) * S_ + col) =
                make_float2(acc[i][j][2] * sc, acc[i][j][3] * sc);
        }
}

// ---------------------------------------------------------------------------
// Softmax: fp32 scores -> attn bf16 hi/lo
// ---------------------------------------------------------------------------
__global__ __launch_bounds__(256) void softmax_kernel() {
    const size_t row = blockIdx.x;
    const float* p = g_S + row * (size_t)S_;
    bf16* oh = g_Ph + row * (size_t)S_;
    bf16* ol = g_Pl + row * (size_t)S_;
    const int tid = threadIdx.x;

    __shared__ float red[256];

    float v[8];
    float m = -INFINITY;
#pragma unroll
    for (int i = 0; i < 8; i++) {
        v[i] = p[tid + i * 256];
        m = fmaxf(m, v[i]);
    }
    red[tid] = m;
    __syncthreads();
    for (int s = 128; s > 0; s >>= 1) {
        if (tid < s) red[tid] = fmaxf(red[tid], red[tid + s]);
        __syncthreads();
    }
    m = red[0];
    __syncthreads();

    float sum = 0.f;
#pragma unroll
    for (int i = 0; i < 8; i++) {
        v[i] = __expf(v[i] - m);
        sum += v[i];
    }
    red[tid] = sum;
    __syncthreads();
    for (int s = 128; s > 0; s >>= 1) {
        if (tid < s) red[tid] += red[tid + s];
        __syncthreads();
    }
    const float inv = 1.0f / red[0];
#pragma unroll
    for (int i = 0; i < 8; i++) {
        bf16 h, l;
        split1(v[i] * inv, h, l);
        oh[tid + i * 256] = h;
        ol[tid + i * 256] = l;
    }
}

// ---------------------------------------------------------------------------
// GEMM 3: out = attn @ V
// ---------------------------------------------------------------------------
__global__ __launch_bounds__(256, 1) void gemm_av_kernel(float* __restrict__ out) {
    const int b = blockIdx.z;
    const bf16* Ah = g_Ph + (size_t)b * S_ * S_;
    const bf16* Al = g_Pl + (size_t)b * S_ * S_;
    const bf16* Bh = g_Vth + (size_t)b * D_ * S_;
    const bf16* Bl = g_Vtl + (size_t)b * D_ * S_;
    const int bm = blockIdx.y * 128, bn = blockIdx.x * 256;

    float acc[4][8][4] = {};
    gemm_core(Ah, Al, S_, Bh, Bl, S_, bm, bn, S_ / BK, acc);

    float* C = out + (size_t)b * S_ * D_;
    const int lane = threadIdx.x & 31, warp = threadIdx.x >> 5;
    const int wm = (warp >> 2) * 64, wn = (warp & 3) * 64;
    const int g = lane >> 2, t = lane & 3;
#pragma unroll
    for (int i = 0; i < 4; i++)
#pragma unroll
        for (int j = 0; j < 8; j++) {
            const int col = bn + wn + 8 * j + 2 * t;
            const int r0 = bm + wm + 16 * i + g;
            *(float2*)(C + (size_t)r0 * D_ + col) =
                make_float2(acc[i][j][0], acc[i][j][1]);
            *(float2*)(C + (size_t)(r0 + 8) * D_ + col) =
                make_float2(acc[i][j][2], acc[i][j][3]);
        }
}

// ---------------------------------------------------------------------------
// Launch (scores moved before transpose_V — same dependencies, and it puts a
// GEMM kernel into the ncu capture slot that kept landing on transpose_V)
// ---------------------------------------------------------------------------
extern "C" void kernel_launch(void* const* d_in, const int* in_sizes, int n_in,
                              void* d_out, int out_size) {
    const float* x  = (const float*)d_in[0];
    const float* Wq = (const float*)d_in[1];
    const float* bq = (const float*)d_in[2];
    const float* Wk = (const float*)d_in[3];
    const float* bk = (const float*)d_in[4];
    const float* Wv = (const float*)d_in[5];
    const float* bv = (const float*)d_in[6];
    float* out = (float*)d_out;

    cudaFuncSetAttribute(gemm_proj_kernel,
                         cudaFuncAttributeMaxDynamicSharedMemorySize, SMEM_DYN);
    cudaFuncSetAttribute(gemm_scores_kernel,
                         cudaFuncAttributeMaxDynamicSharedMemorySize, SMEM_DYN);
    cudaFuncSetAttribute(gemm_av_kernel,
                         cudaFuncAttributeMaxDynamicSharedMemorySize, SMEM_DYN);

    convert_x_kernel<<<(MS * D_) / 1024, 256>>>(x);
    convert_Wt_kernel<<<dim3(32, 32, 3), dim3(32, 8)>>>(Wq, Wk, Wv);

    gemm_proj_kernel<<<dim3(D_ / 256, MS / 128, 3), 256, SMEM_DYN>>>(bq, bk, bv);

    gemm_scores_kernel<<<dim3(S_ / 256, S_ / 128, B_), 256, SMEM_DYN>>>();

    transpose_V_kernel<<<dim3(S_ / 32, D_ / 32, B_), dim3(32, 8)>>>();

    softmax_kernel<<<B_ * S_, 256>>>();

    gemm_av_kernel<<<dim3(D_ / 256, S_ / 128, B_), 256, SMEM_DYN>>>(out);
}

// round 9
// speedup vs baseline: 3.1815x; 1.3379x over previous
#include <cuda_runtime.h>
#include <cuda_bf16.h>
#include <stdint.h>
#include <math.h>

#define B_  4
#define S_  2048
#define D_  1024
#define MS  (B_*S_)
#define BK  16
#define NSTG 4
#define OFF_AL 4096
#define OFF_BH 8192
#define OFF_BL 16384
#define STAGE_B 24576                  // 24 KB: [Ah 4K][Al 4K][Bh 8K][Bl 8K]
#define SMEM_DYN (NSTG*STAGE_B)        // 96 KB

typedef __nv_bfloat16 bf16;

// ---------------------------------------------------------------------------
// Packed operand layout ("stage image"): [blk128][kchunk][swizzled 128x16]
// element offset of (global row r, k) given KCtot = kdim/16
// ---------------------------------------------------------------------------
__host__ __device__ __forceinline__ size_t pk_off(int r, int k, int KCtot) {
    const int u = (r & 127) * 2 + (((k >> 3) & 1) ^ ((r >> 2) & 1));
    return ((size_t)((r >> 7) * KCtot + (k >> 4)) * 2048) + (size_t)u * 8 + (k & 7);
}

// smem byte offset inside one 128x16 array (same swizzle)
__device__ __forceinline__ uint32_t swzb(int row, int chunk) {
    return (uint32_t)((row * 2 + (chunk ^ ((row >> 2) & 1))) * 16);
}

// ---------------------------------------------------------------------------
// Device-global scratch (allocation-free rule)
// ---------------------------------------------------------------------------
__device__ bf16 g_xh[MS * D_], g_xl[MS * D_];                // packed, KCtot=64
__device__ bf16 g_Wth[3][D_ * D_], g_Wtl[3][D_ * D_];        // packed W^T, KCtot=64
__device__ bf16 g_Qh[MS * D_], g_Ql[MS * D_];                // packed, KCtot=64
__device__ bf16 g_Kh[MS * D_], g_Kl[MS * D_];                // packed, KCtot=64
__device__ bf16 g_Vh[MS * D_], g_Vl[MS * D_];                // PLAIN row-major [m][d]
__device__ bf16 g_Vth[MS * D_], g_Vtl[MS * D_];              // packed V^T, KCtot=128
__device__ float g_S[(size_t)B_ * S_ * S_];                  // plain fp32
__device__ bf16 g_Ph[(size_t)B_ * S_ * S_], g_Pl[(size_t)B_ * S_ * S_]; // packed, KCtot=128

// ---------------------------------------------------------------------------
// Helpers
// ---------------------------------------------------------------------------
__device__ __forceinline__ void split1(float v, bf16& h, bf16& l) {
    h = __float2bfloat16_rn(v);
    l = __float2bfloat16_rn(v - __bfloat162float(h));
}

__device__ __forceinline__ void ldsm4(uint32_t r[4], uint32_t a) {
    asm volatile("ldmatrix.sync.aligned.m8n8.x4.shared.b16 {%0,%1,%2,%3}, [%4];"
                 : "=r"(r[0]), "=r"(r[1]), "=r"(r[2]), "=r"(r[3]) : "r"(a));
}

__device__ __forceinline__ void mma_bf16(float c[4], const uint32_t a[4],
                                         const uint32_t b0, const uint32_t b1) {
    asm volatile(
        "mma.sync.aligned.m16n8k16.row.col.f32.bf16.bf16.f32 "
        "{%0,%1,%2,%3},{%4,%5,%6,%7},{%8,%9},{%0,%1,%2,%3};"
        : "+f"(c[0]), "+f"(c[1]), "+f"(c[2]), "+f"(c[3])
        : "r"(a[0]), "r"(a[1]), "r"(a[2]), "r"(a[3]), "r"(b0), "r"(b1));
}

__device__ __forceinline__ void bulk4k(uint32_t dst, const void* src, uint32_t mbar) {
    asm volatile(
        "cp.async.bulk.shared::cluster.global.mbarrier::complete_tx::bytes "
        "[%0], [%1], 4096, [%2];"
        :: "r"(dst), "l"(src), "r"(mbar) : "memory");
}

__device__ __forceinline__ void mbar_wait(uint32_t mbar, uint32_t parity) {
    uint32_t done;
    asm volatile(
        "{\n\t.reg .pred p;\n\t"
        "mbarrier.try_wait.parity.acquire.cta.shared::cta.b64 p, [%1], %2;\n\t"
        "selp.b32 %0, 1, 0, p;\n\t}"
        : "=r"(done) : "r"(mbar), "r"(parity) : "memory");
    if (!done) {
        asm volatile(
            "{\n\t.reg .pred P1;\n\t"
            "WAIT_LOOP_%=:\n\t"
            "mbarrier.try_wait.parity.acquire.cta.shared::cta.b64 P1, [%0], %1, 0x989680;\n\t"
            "@P1 bra.uni WAIT_DONE_%=;\n\t"
            "bra.uni WAIT_LOOP_%=;\n\t"
            "WAIT_DONE_%=:\n\t}"
            :: "r"(mbar), "r"(parity) : "memory");
    }
}

// ---------------------------------------------------------------------------
// Stage issue: one thread, 6 x 4KB bulk copies into one mbarrier
// ---------------------------------------------------------------------------
__device__ __forceinline__ void issue_stage(uint32_t st, uint32_t mbar,
        const bf16* __restrict__ Ah, const bf16* __restrict__ Al,
        const bf16* __restrict__ Bh, const bf16* __restrict__ Bl,
        int mblk, int nblk0, int kc, int KCA, int KCB) {
    asm volatile("mbarrier.arrive.expect_tx.shared.b64 _, [%0], %1;"
                 :: "r"(mbar), "r"(24576u) : "memory");
    const size_t ao = ((size_t)mblk * KCA + kc) * 2048;
    bulk4k(st,              Ah + ao, mbar);
    bulk4k(st + OFF_AL,     Al + ao, mbar);
    const size_t b0 = ((size_t)nblk0 * KCB + kc) * 2048;
    const size_t b1 = ((size_t)(nblk0 + 1) * KCB + kc) * 2048;
    bulk4k(st + OFF_BH,        Bh + b0, mbar);
    bulk4k(st + OFF_BH + 4096, Bh + b1, mbar);
    bulk4k(st + OFF_BL,        Bl + b0, mbar);
    bulk4k(st + OFF_BL + 4096, Bl + b1, mbar);
}

// ---------------------------------------------------------------------------
// GEMM mainloop: C 128x256 block from packed operands.
// Ring discipline: chunk j lives in slot (j & 3). Prologue fills ALL 4 slots
// with chunks 0..3; in-loop, after the barrier that retires slot s = kt&3,
// tid0 refills slot s with chunk kt+NSTG (whose slot IS s). Wait parity for
// slot s at iteration kt is (kt>>2)&1 = fill count mod 2.
// acc += Ah*Bh + Al*Bh + Ah*Bl (term-major). 8 warps 2(m) x 4(n), 64x64 tiles.
// ---------------------------------------------------------------------------
__device__ void gemm_core(
    const bf16* __restrict__ Ahp, const bf16* __restrict__ Alp,
    const bf16* __restrict__ Bhp, const bf16* __restrict__ Blp,
    int mblk, int nblk0, int KC, int KCA, int KCB, float acc[4][8][4])
{
    extern __shared__ char dsm[];
    __shared__ uint64_t mbars[NSTG];
    const uint32_t sb = (uint32_t)__cvta_generic_to_shared(dsm);
    const uint32_t mb0 = (uint32_t)__cvta_generic_to_shared(mbars);

    const int tid = threadIdx.x, lane = tid & 31, warp = tid >> 5;
    const int wm = (warp >> 2) * 64, wn = (warp & 3) * 64;

    // ldmatrix lane mappings (validated rounds 3/5/6/7)
    const int arow = (lane & 7) + 8 * ((lane >> 3) & 1);
    const int achk = lane >> 4;
    const int brow = (lane & 7) + 8 * ((lane >> 4) & 1);
    const int bchk = (lane >> 3) & 1;

    if (tid == 0) {
#pragma unroll
        for (int s = 0; s < NSTG; s++)
            asm volatile("mbarrier.init.shared.b64 [%0], %1;"
                         :: "r"(mb0 + 8 * s), "r"(1u) : "memory");
    }
    __syncthreads();

    if (tid == 0) {
#pragma unroll
        for (int i = 0; i < NSTG; i++)          // fill ALL slots: chunks 0..3
            issue_stage(sb + i * STAGE_B, mb0 + 8 * i,
                        Ahp, Alp, Bhp, Blp, mblk, nblk0, i, KCA, KCB);
    }

    const int bblk = wn >> 7;          // which 128-row B block this warp reads
    const int bri = (wn & 127);        // base row within that block

    for (int kt = 0; kt < KC; kt++) {
        const int s = kt & 3;
        mbar_wait(mb0 + 8 * s, (kt >> 2) & 1);

        const uint32_t st = sb + s * STAGE_B;

        uint32_t ah[4][4], al[4][4], bh[4][4], bl[4][4];
#pragma unroll
        for (int i = 0; i < 4; i++) {
            const uint32_t o = swzb(wm + 16 * i + arow, achk);
            ldsm4(ah[i], st + o);
            ldsm4(al[i], st + OFF_AL + o);
        }
#pragma unroll
        for (int p = 0; p < 4; p++) {
            const uint32_t o = bblk * 4096 + swzb(bri + 16 * p + brow, bchk);
            ldsm4(bh[p], st + OFF_BH + o);
            ldsm4(bl[p], st + OFF_BL + o);
        }

        __syncthreads();   // all warps done reading slot s

        const int j = kt + NSTG;       // (j & 3) == s — refill the freed slot
        if (tid == 0 && j < KC)
            issue_stage(st, mb0 + 8 * s, Ahp, Alp, Bhp, Blp,
                        mblk, nblk0, j, KCA, KCB);

        // term 0: Ah*Bh
#pragma unroll
        for (int i = 0; i < 4; i++)
#pragma unroll
            for (int jj = 0; jj < 8; jj++) {
                const int p = jj >> 1, q = (jj & 1) * 2;
                mma_bf16(acc[i][jj], ah[i], bh[p][q], bh[p][q + 1]);
            }
        // term 1: Al*Bh
#pragma unroll
        for (int i = 0; i < 4; i++)
#pragma unroll
            for (int jj = 0; jj < 8; jj++) {
                const int p = jj >> 1, q = (jj & 1) * 2;
                mma_bf16(acc[i][jj], al[i], bh[p][q], bh[p][q + 1]);
            }
        // term 2: Ah*Bl
#pragma unroll
        for (int i = 0; i < 4; i++)
#pragma unroll
            for (int jj = 0; jj < 8; jj++) {
                const int p = jj >> 1, q = (jj & 1) * 2;
                mma_bf16(acc[i][jj], ah[i], bl[p][q], bl[p][q + 1]);
            }
    }
}

// ---------------------------------------------------------------------------
// Conversion kernels
// ---------------------------------------------------------------------------
__global__ void convert_x_kernel(const float* __restrict__ x) {
    size_t i = ((size_t)blockIdx.x * 256 + threadIdx.x) * 4;
    const int m = (int)(i / D_), k = (int)(i % D_);
    float4 v = *(const float4*)(x + i);
    bf16 h0, l0, h1, l1, h2, l2, h3, l3;
    split1(v.x, h0, l0); split1(v.y, h1, l1);
    split1(v.z, h2, l2); split1(v.w, h3, l3);
    const size_t o = pk_off(m, k, D_ / 16);
    *(__nv_bfloat162*)(g_xh + o)     = __halves2bfloat162(h0, h1);
    *(__nv_bfloat162*)(g_xh + o + 2) = __halves2bfloat162(h2, h3);
    *(__nv_bfloat162*)(g_xl + o)     = __halves2bfloat162(l0, l1);
    *(__nv_bfloat162*)(g_xl + o + 2) = __halves2bfloat162(l2, l3);
}

__global__ void convert_Wt_kernel(const float* __restrict__ Wq,
                                  const float* __restrict__ Wk,
                                  const float* __restrict__ Wv) {
    const float* W = blockIdx.z == 0 ? Wq : blockIdx.z == 1 ? Wk : Wv;
    bf16* Oh = g_Wth[blockIdx.z];
    bf16* Ol = g_Wtl[blockIdx.z];
    __shared__ float t[32][33];
    const int k0 = blockIdx.y * 32, n0 = blockIdx.x * 32;
    const int tx = threadIdx.x, ty = threadIdx.y;
#pragma unroll
    for (int r = 0; r < 32; r += 8)
        t[ty + r][tx] = W[(size_t)(k0 + ty + r) * D_ + n0 + tx];
    __syncthreads();
#pragma unroll
    for (int r = 0; r < 32; r += 8) {
        float v = t[tx][ty + r];
        bf16 h, l; split1(v, h, l);
        const size_t o = pk_off(n0 + ty + r, k0 + tx, D_ / 16);
        Oh[o] = h; Ol[o] = l;
    }
}

__global__ void transpose_V_kernel() {
    __shared__ bf16 th[32][33], tl[32][33];
    const int b = blockIdx.z;
    const int t0 = blockIdx.x * 32, d0 = blockIdx.y * 32;
    const int tx = threadIdx.x, ty = threadIdx.y;
    const bf16* Vh = g_Vh + (size_t)b * S_ * D_;
    const bf16* Vl = g_Vl + (size_t)b * S_ * D_;
#pragma unroll
    for (int r = 0; r < 32; r += 8) {
        size_t o = (size_t)(t0 + ty + r) * D_ + d0 + tx;
        th[ty + r][tx] = Vh[o];
        tl[ty + r][tx] = Vl[o];
    }
    __syncthreads();
#pragma unroll
    for (int r = 0; r < 32; r += 8) {
        const size_t o = pk_off(b * D_ + d0 + ty + r, t0 + tx, S_ / 16);
        g_Vth[o] = th[tx][ty + r];
        g_Vtl[o] = tl[tx][ty + r];
    }
}

// ---------------------------------------------------------------------------
// GEMM 1: QKV projection. Q,K written packed; V written plain row-major.
// ---------------------------------------------------------------------------
__global__ __launch_bounds__(256, 1) void gemm_proj_kernel(
    const float* __restrict__ bqp, const float* __restrict__ bkp,
    const float* __restrict__ bvp) {
    const int z = blockIdx.z;
    const float* bias = z == 0 ? bqp : z == 1 ? bkp : bvp;
    const int bm = blockIdx.y * 128, bn = blockIdx.x * 256;

    float acc[4][8][4] = {};
    gemm_core(g_xh, g_xl, g_Wth[z], g_Wtl[z],
              blockIdx.y, blockIdx.x * 2, D_ / BK, D_ / 16, D_ / 16, acc);

    const int lane = threadIdx.x & 31, warp = threadIdx.x >> 5;
    const int wm = (warp >> 2) * 64, wn = (warp & 3) * 64;
    const int g = lane >> 2, t = lane & 3;
#pragma unroll
    for (int i = 0; i < 4; i++)
#pragma unroll
        for (int j = 0; j < 8; j++) {
            const int col = bn + wn + 8 * j + 2 * t;
            const float b0 = bias[col], b1 = bias[col + 1];
#pragma unroll
            for (int h2 = 0; h2 < 2; h2++) {
                const int r0 = bm + wm + 16 * i + g + 8 * h2;
                bf16 h0, l0, h1, l1;
                split1(acc[i][j][2 * h2 + 0] + b0, h0, l0);
                split1(acc[i][j][2 * h2 + 1] + b1, h1, l1);
                if (z < 2) {
                    bf16* Ch = z == 0 ? g_Qh : g_Kh;
                    bf16* Cl = z == 0 ? g_Ql : g_Kl;
                    const size_t o = pk_off(r0, col, D_ / 16);
                    *(__nv_bfloat162*)(Ch + o) = __halves2bfloat162(h0, h1);
                    *(__nv_bfloat162*)(Cl + o) = __halves2bfloat162(l0, l1);
                } else {
                    const size_t o = (size_t)r0 * D_ + col;
                    *(__nv_bfloat162*)(g_Vh + o) = __halves2bfloat162(h0, h1);
                    *(__nv_bfloat162*)(g_Vl + o) = __halves2bfloat162(l0, l1);
                }
            }
        }
}

// ---------------------------------------------------------------------------
// GEMM 2: scores = (Q @ K^T) * scale  (fp32 plain out)
// ---------------------------------------------------------------------------
__global__ __launch_bounds__(256, 1) void gemm_scores_kernel() {
    const int b = blockIdx.z;
    const int bm = blockIdx.y * 128, bn = blockIdx.x * 256;

    float acc[4][8][4] = {};
    gemm_core(g_Qh, g_Ql, g_Kh, g_Kl,
              b * 16 + blockIdx.y, b * 16 + blockIdx.x * 2,
              D_ / BK, D_ / 16, D_ / 16, acc);

    float* C = g_S + (size_t)b * S_ * S_;
    const int lane = threadIdx.x & 31, warp = threadIdx.x >> 5;
    const int wm = (warp >> 2) * 64, wn = (warp & 3) * 64;
    const int g = lane >> 2, t = lane & 3;
    const float sc = 0.03125f;
#pragma unroll
    for (int i = 0; i < 4; i++)
#pragma unroll
        for (int j = 0; j < 8; j++) {
            const int col = bn + wn + 8 * j + 2 * t;
            const int r0 = bm + wm + 16 * i + g;
            *(float2*)(C + (size_t)r0 * S_ + col) =
                make_float2(acc[i][j][0] * sc, acc[i][j][1] * sc);
            *(float2*)(C + (size_t)(r0 + 8) * S_ + col) =
                make_float2(acc[i][j][2] * sc, acc[i][j][3] * sc);
        }
}

// ---------------------------------------------------------------------------
// Softmax: fp32 scores -> packed attn bf16 hi/lo
// ---------------------------------------------------------------------------
__global__ __launch_bounds__(256) void softmax_kernel() {
    const int row = blockIdx.x;                 // global P row 0..8191
    const float* p = g_S + (size_t)row * S_;
    const int tid = threadIdx.x;

    __shared__ float red[256];

    float v[8];
    float m = -INFINITY;
#pragma unroll
    for (int i = 0; i < 8; i++) {
        v[i] = p[tid + i * 256];
        m = fmaxf(m, v[i]);
    }
    red[tid] = m;
    __syncthreads();
    for (int s = 128; s > 0; s >>= 1) {
        if (tid < s) red[tid] = fmaxf(red[tid], red[tid + s]);
        __syncthreads();
    }
    m = red[0];
    __syncthreads();

    float sum = 0.f;
#pragma unroll
    for (int i = 0; i < 8; i++) {
        v[i] = __expf(v[i] - m);
        sum += v[i];
    }
    red[tid] = sum;
    __syncthreads();
    for (int s = 128; s > 0; s >>= 1) {
        if (tid < s) red[tid] += red[tid + s];
        __syncthreads();
    }
    const float inv = 1.0f / red[0];
#pragma unroll
    for (int i = 0; i < 8; i++) {
        bf16 h, l;
        split1(v[i] * inv, h, l);
        const size_t o = pk_off(row, tid + i * 256, S_ / 16);
        g_Ph[o] = h;
        g_Pl[o] = l;
    }
}

// ---------------------------------------------------------------------------
// GEMM 3: out = attn @ V  (fp32 plain out)
// ---------------------------------------------------------------------------
__global__ __launch_bounds__(256, 1) void gemm_av_kernel(float* __restrict__ out) {
    const int b = blockIdx.z;
    const int bm = blockIdx.y * 128, bn = blockIdx.x * 256;

    float acc[4][8][4] = {};
    gemm_core(g_Ph, g_Pl, g_Vth, g_Vtl,
              b * 16 + blockIdx.y, b * 8 + blockIdx.x * 2,
              S_ / BK, S_ / 16, S_ / 16, acc);

    float* C = out + (size_t)b * S_ * D_;
    const int lane = threadIdx.x & 31, warp = threadIdx.x >> 5;
    const int wm = (warp >> 2) * 64, wn = (warp & 3) * 64;
    const int g = lane >> 2, t = lane & 3;
#pragma unroll
    for (int i = 0; i < 4; i++)
#pragma unroll
        for (int j = 0; j < 8; j++) {
            const int col = bn + wn + 8 * j + 2 * t;
            const int r0 = bm + wm + 16 * i + g;
            *(float2*)(C + (size_t)r0 * D_ + col) =
                make_float2(acc[i][j][0], acc[i][j][1]);
            *(float2*)(C + (size_t)(r0 + 8) * D_ + col) =
                make_float2(acc[i][j][2], acc[i][j][3]);
        }
}

// ---------------------------------------------------------------------------
// Launch
// ---------------------------------------------------------------------------
extern "C" void kernel_launch(void* const* d_in, const int* in_sizes, int n_in,
                              void* d_out, int out_size) {
    const float* x  = (const float*)d_in[0];
    const float* Wq = (const float*)d_in[1];
    const float* bq = (const float*)d_in[2];
    const float* Wk = (const float*)d_in[3];
    const float* bk = (const float*)d_in[4];
    const float* Wv = (const float*)d_in[5];
    const float* bv = (const float*)d_in[6];
    float* out = (float*)d_out;

    cudaFuncSetAttribute(gemm_proj_kernel,
                         cudaFuncAttributeMaxDynamicSharedMemorySize, SMEM_DYN);
    cudaFuncSetAttribute(gemm_scores_kernel,
                         cudaFuncAttributeMaxDynamicSharedMemorySize, SMEM_DYN);
    cudaFuncSetAttribute(gemm_av_kernel,
                         cudaFuncAttributeMaxDynamicSharedMemorySize, SMEM_DYN);

    convert_x_kernel<<<(MS * D_) / 1024, 256>>>(x);
    convert_Wt_kernel<<<dim3(32, 32, 3), dim3(32, 8)>>>(Wq, Wk, Wv);

    gemm_proj_kernel<<<dim3(D_ / 256, MS / 128, 3), 256, SMEM_DYN>>>(bq, bk, bv);

    gemm_scores_kernel<<<dim3(S_ / 256, S_ / 128, B_), 256, SMEM_DYN>>>();

    transpose_V_kernel<<<dim3(S_ / 32, D_ / 32, B_), dim3(32, 8)>>>();

    softmax_kernel<<<B_ * S_, 256>>>();

    gemm_av_kernel<<<dim3(D_ / 256, S_ / 128, B_), 256, SMEM_DYN>>>(out);
}